// round 1
// baseline (speedup 1.0000x reference)
#include <cuda_runtime.h>
#include <math.h>

// Problem shapes (fixed by the dataset)
#define N_ROWS 8192
#define DIM    512
#define KPOS   8
#define NCLS   1000

// Tiling
#define SPLIT  8                  // column splits -> grid.y
#define BM     128
#define BN     128
#define BK     16
#define JCOLS  (N_ROWS / SPLIT)   // 1024 columns per CTA
#define JT     (JCOLS / BN)       // 8 column tiles per CTA

// exp(x/tau) = 2^(x * log2(e)/tau)
#define C2 20.60992915555662f     // log2(e) / 0.07

// ---------------- scratch (no allocations allowed) ----------------
__device__ float g_pos[SPLIT][N_ROWS];
__device__ float g_neg[SPLIT][N_ROWS];
__device__ int   g_cnt[NCLS];
__device__ float g_invc[NCLS];
__device__ float g_loss[N_ROWS];

// ---------------- packed f32x2 helpers (Blackwell FFMA2) ----------------
__device__ __forceinline__ unsigned long long pack2(float x) {
    unsigned long long r;
    asm("mov.b64 %0, {%1, %1};" : "=l"(r) : "f"(x));
    return r;
}
__device__ __forceinline__ void ffma2(unsigned long long& d,
                                      unsigned long long a,
                                      unsigned long long b) {
    asm("fma.rn.f32x2 %0, %1, %2, %0;" : "+l"(d) : "l"(a), "l"(b));
}
__device__ __forceinline__ float2 unpack2(unsigned long long v) {
    float2 f;
    asm("mov.b64 {%0, %1}, %2;" : "=f"(f.x), "=f"(f.y) : "l"(v));
    return f;
}
__device__ __forceinline__ float ex2(float x) {
    float r;
    asm("ex2.approx.ftz.f32 %0, %1;" : "=f"(r) : "f"(x));
    return r;
}

// ---------------- kernel 1: bincount + reciprocals ----------------
__global__ void k_bincount(const int* __restrict__ y) {
    __shared__ int sc[NCLS];
    for (int c = threadIdx.x; c < NCLS; c += blockDim.x) sc[c] = 0;
    __syncthreads();
    for (int i = threadIdx.x; i < N_ROWS; i += blockDim.x)
        atomicAdd(&sc[y[i]], 1);
    __syncthreads();
    for (int c = threadIdx.x; c < NCLS; c += blockDim.x) {
        int v = sc[c];
        g_cnt[c]  = v;
        g_invc[c] = v > 0 ? 1.0f / (float)v : 0.0f;
    }
}

// ---------------- kernel 2: fused Gram + masked-exp reduction ----------------
// CTA (bx, by): rows [bx*128, bx*128+128), cols [by*1024, by*1024+1024)
__global__ __launch_bounds__(256)
void k_gram(const float* __restrict__ q, const int* __restrict__ y) {
    __shared__ float As[BK][BM];
    __shared__ float Bs[BK][BN];
    __shared__ int   ysh[BN];
    __shared__ float wsh[BN];
    __shared__ float red[BM][16];

    const int tid = threadIdx.x;
    const int tx  = tid & 15;     // column group (8 cols each)
    const int ty  = tid >> 4;     // row group    (8 rows each)
    const int i0    = blockIdx.x * BM;
    const int jbase = blockIdx.y * JCOLS;

    int yi[8];
#pragma unroll
    for (int r = 0; r < 8; ++r) yi[r] = y[i0 + ty * 8 + r];

    float pos[8], neg[8];
#pragma unroll
    for (int r = 0; r < 8; ++r) { pos[r] = 0.0f; neg[r] = 0.0f; }

    for (int jt = 0; jt < JT; ++jt) {
        const int j0 = jbase + jt * BN;

        __syncthreads();                       // previous epilogue done (ysh reuse)
        if (tid < BN) {
            int yy = y[j0 + tid];
            ysh[tid] = yy;
            wsh[tid] = g_invc[yy];
        }

        unsigned long long acc[8][4];
#pragma unroll
        for (int r = 0; r < 8; ++r)
#pragma unroll
            for (int p = 0; p < 4; ++p) acc[r][p] = 0ull;

        for (int d0 = 0; d0 < DIM; d0 += BK) {
            __syncthreads();                   // previous compute done before overwrite
#pragma unroll
            for (int l = 0; l < 2; ++l) {
                int idx = tid + l * 256;
                int r   = idx >> 2;
                int cg  = (idx & 3) * 4;
                float4 va = *(const float4*)(q + (size_t)(i0 + r) * DIM + d0 + cg);
                As[cg + 0][r] = va.x; As[cg + 1][r] = va.y;
                As[cg + 2][r] = va.z; As[cg + 3][r] = va.w;
                float4 vb = *(const float4*)(q + (size_t)(j0 + r) * DIM + d0 + cg);
                Bs[cg + 0][r] = vb.x; Bs[cg + 1][r] = vb.y;
                Bs[cg + 2][r] = vb.z; Bs[cg + 3][r] = vb.w;
            }
            __syncthreads();
#pragma unroll
            for (int d = 0; d < BK; ++d) {
                float4 a0 = *(const float4*)&As[d][ty * 8];
                float4 a1 = *(const float4*)&As[d][ty * 8 + 4];
                float4 b0 = *(const float4*)&Bs[d][tx * 8];
                float4 b1 = *(const float4*)&Bs[d][tx * 8 + 4];
                unsigned long long bb[4];
                bb[0] = ((const unsigned long long*)&b0)[0];
                bb[1] = ((const unsigned long long*)&b0)[1];
                bb[2] = ((const unsigned long long*)&b1)[0];
                bb[3] = ((const unsigned long long*)&b1)[1];
                float av[8] = {a0.x, a0.y, a0.z, a0.w, a1.x, a1.y, a1.z, a1.w};
#pragma unroll
                for (int r = 0; r < 8; ++r) {
                    unsigned long long aa = pack2(av[r]);
#pragma unroll
                    for (int p = 0; p < 4; ++p) ffma2(acc[r][p], aa, bb[p]);
                }
            }
        }

        // epilogue: masked exp accumulation (faithful to the *mask==0 -> -inf quirk)
#pragma unroll
        for (int r = 0; r < 8; ++r) {
            const int ig = i0 + ty * 8 + r;
#pragma unroll
            for (int p = 0; p < 4; ++p) {
                float2 s2 = unpack2(acc[r][p]);
                float ss[2] = {s2.x, s2.y};
#pragma unroll
                for (int h = 0; h < 2; ++h) {
                    int   jl  = tx * 8 + p * 2 + h;
                    int   jg  = j0 + jl;
                    float dot = ss[h];
                    if (dot != 0.0f) {                 // exact-zero -> masked to -inf in ref
                        float e = ex2(dot * C2);       // exp(dot/tau)
                        if (ysh[jl] == yi[r]) {
                            if (jg != ig) pos[r] += e; // in-batch positive (excl. self)
                        } else {
                            neg[r] += e * wsh[jl];     // class-frequency-weighted negative
                        }
                    }
                }
            }
        }
    }

    // deterministic cross-thread reduction (16 threads share each row)
    __syncthreads();
#pragma unroll
    for (int r = 0; r < 8; ++r) red[ty * 8 + r][tx] = pos[r];
    __syncthreads();
    if (tid < BM) {
        float s = 0.0f;
#pragma unroll
        for (int x = 0; x < 16; ++x) s += red[tid][x];
        g_pos[blockIdx.y][i0 + tid] = s;
    }
    __syncthreads();
#pragma unroll
    for (int r = 0; r < 8; ++r) red[ty * 8 + r][tx] = neg[r];
    __syncthreads();
    if (tid < BM) {
        float s = 0.0f;
#pragma unroll
        for (int x = 0; x < 16; ++x) s += red[tid][x];
        g_neg[blockIdx.y][i0 + tid] = s;
    }
}

// ---------------- kernel 3: k-positive sims + per-row loss ----------------
__global__ void k_rowloss(const float* __restrict__ q,
                          const float* __restrict__ kv,
                          const int* __restrict__ y) {
    const int warp = threadIdx.x >> 5;
    const int lane = threadIdx.x & 31;
    const int i = blockIdx.x * 8 + warp;

    const float* qi = q + (size_t)i * DIM;
    float esum = 0.0f;
    for (int kk = 0; kk < KPOS; ++kk) {
        const float* kp = kv + ((size_t)i * KPOS + kk) * DIM;
        float acc = 0.0f;
#pragma unroll
        for (int e = 0; e < DIM / 32; ++e)
            acc = fmaf(qi[lane + 32 * e], kp[lane + 32 * e], acc);
#pragma unroll
        for (int off = 16; off > 0; off >>= 1)
            acc += __shfl_down_sync(0xffffffffu, acc, off);
        if (lane == 0) esum += ex2(acc * C2);
    }
    if (lane == 0) {
        float pt = esum, nt = 0.0f;
#pragma unroll
        for (int sp = 0; sp < SPLIT; ++sp) {
            pt += g_pos[sp][i];
            nt += g_neg[sp][i];
        }
        float num = logf(pt);
        float den = logf(nt);
        float cnt = (float)(g_cnt[y[i]] - 1 + KPOS);  // same_class_counts
        g_loss[i] = -(num - den) / cnt;
    }
}

// ---------------- kernel 4: deterministic mean ----------------
__global__ void k_reduce(float* __restrict__ out) {
    __shared__ float sm[1024];
    float s = 0.0f;
    for (int i = threadIdx.x; i < N_ROWS; i += 1024) s += g_loss[i];
    sm[threadIdx.x] = s;
    __syncthreads();
    for (int st = 512; st > 0; st >>= 1) {
        if (threadIdx.x < st) sm[threadIdx.x] += sm[threadIdx.x + st];
        __syncthreads();
    }
    if (threadIdx.x == 0) out[0] = sm[0] * (1.0f / (float)N_ROWS);
}

// ---------------- launch ----------------
extern "C" void kernel_launch(void* const* d_in, const int* in_sizes, int n_in,
                              void* d_out, int out_size) {
    const float* q  = nullptr;
    const float* kv = nullptr;
    const int*   y  = nullptr;
    for (int i = 0; i < n_in; ++i) {
        long long sz = in_sizes[i];
        if (sz == (long long)N_ROWS * DIM)             q  = (const float*)d_in[i];
        else if (sz == (long long)N_ROWS * KPOS * DIM) kv = (const float*)d_in[i];
        else if (sz == (long long)N_ROWS)              y  = (const int*)d_in[i];
    }
    float* out = (float*)d_out;

    k_bincount<<<1, 1024>>>(y);
    k_gram<<<dim3(N_ROWS / BM, SPLIT), 256>>>(q, y);
    k_rowloss<<<N_ROWS / 8, 256>>>(q, kv, y);
    k_reduce<<<1, 1024>>>(out);
}

// round 8
// speedup vs baseline: 5.5146x; 5.5146x over previous
#include <cuda_runtime.h>
#include <math.h>
#include <stdint.h>

// ---------------- problem shapes ----------------
#define N_ROWS 8192
#define DIM    512
#define KPOS   8
#define NCLS   1000
#define C2     20.60992915555662f   // log2(e)/0.07

// ---------------- GEMM tiling ----------------
#define TMC 128                    // CTA M tile
#define TNC 256                    // CTA N tile
#define KCH 16                     // K floats per stage
#define NKS (DIM / KCH)            // 32 k-steps
#define NRB (N_ROWS / TMC)         // 64
#define NSPL (N_ROWS / TNC)        // 32 column splits
#define A_ST_BYTES (TMC * KCH * 4) // 8192
#define B_ST_BYTES (TNC * KCH * 4) // 16384
#define STAGE_BYTES (A_ST_BYTES + B_ST_BYTES)  // 24576
#define NSTAGES 4
#define DSM_BYTES (NSTAGES * STAGE_BYTES)      // 98304

// ---------------- scratch ----------------
__device__ float g_qtf[N_ROWS * DIM];      // tf32-rounded Q, row-major
__device__ float g_pos[NSPL][N_ROWS];
__device__ float g_neg[NSPL][N_ROWS];
__device__ int   g_cnt[NCLS];
__device__ float g_invc[NCLS];
__device__ float g_loss[N_ROWS];

// ---------------- helpers ----------------
__device__ __forceinline__ uint32_t s2u(const void* p) {
    uint32_t a;
    asm("{ .reg .u64 t; cvta.to.shared.u64 t, %1; cvt.u32.u64 %0, t; }" : "=r"(a) : "l"(p));
    return a;
}
__device__ __forceinline__ void lds128(uint32_t* r, uint32_t a) {
    asm volatile("ld.shared.v4.b32 {%0,%1,%2,%3}, [%4];"
                 : "=r"(r[0]), "=r"(r[1]), "=r"(r[2]), "=r"(r[3]) : "r"(a));
}
__device__ __forceinline__ void cpasync16(uint32_t dst, const void* src) {
    asm volatile("cp.async.cg.shared.global [%0], [%1], 16;" :: "r"(dst), "l"(src) : "memory");
}
__device__ __forceinline__ void cp_commit() {
    asm volatile("cp.async.commit_group;" ::: "memory");
}
__device__ __forceinline__ float ex2f(float x) {
    float r;
    asm("ex2.approx.ftz.f32 %0, %1;" : "=f"(r) : "f"(x));
    return r;
}
#define MMA_TF32(c, a0, a1, a2, a3, b0, b1)                                   \
    asm volatile(                                                             \
        "mma.sync.aligned.m16n8k8.row.col.f32.tf32.tf32.f32 "                 \
        "{%0,%1,%2,%3},{%4,%5,%6,%7},{%8,%9},{%0,%1,%2,%3};"                  \
        : "+f"(c[0]), "+f"(c[1]), "+f"(c[2]), "+f"(c[3])                      \
        : "r"(a0), "r"(a1), "r"(a2), "r"(a3), "r"(b0), "r"(b1))

// ---------------- kernel 0: bincount + reciprocals ----------------
__global__ void k_bincount(const int* __restrict__ y) {
    __shared__ int sc[NCLS];
    for (int c = threadIdx.x; c < NCLS; c += blockDim.x) sc[c] = 0;
    __syncthreads();
    for (int i = threadIdx.x; i < N_ROWS; i += blockDim.x)
        atomicAdd(&sc[y[i]], 1);
    __syncthreads();
    for (int c = threadIdx.x; c < NCLS; c += blockDim.x) {
        int v = sc[c];
        g_cnt[c]  = v;
        g_invc[c] = v > 0 ? 1.0f / (float)v : 0.0f;
    }
}

// ---------------- kernel 1: tf32-round Q (row-major) ----------------
__global__ void k_prep(const float* __restrict__ q) {
    int gid = blockIdx.x * blockDim.x + threadIdx.x;  // one float4
    float4 v = ((const float4*)q)[gid];
    uint32_t o0, o1, o2, o3;
    asm("cvt.rn.tf32.f32 %0, %1;" : "=r"(o0) : "f"(v.x));
    asm("cvt.rn.tf32.f32 %0, %1;" : "=r"(o1) : "f"(v.y));
    asm("cvt.rn.tf32.f32 %0, %1;" : "=r"(o2) : "f"(v.z));
    asm("cvt.rn.tf32.f32 %0, %1;" : "=r"(o3) : "f"(v.w));
    ((uint4*)g_qtf)[gid] = make_uint4(o0, o1, o2, o3);
}

// ---------------- kernel 2: mma.sync tf32 Gram + fused masked-exp epilogue ----------------
// CTA: rows [bx*128, +128), cols [by*256, +256). 8 warps = 2(M) x 4(N), warp tile 64x64.
__global__ __launch_bounds__(256, 1)
void k_gram(const int* __restrict__ y) {
    extern __shared__ __align__(16) char dsm_raw[];
    __shared__ int   ysh[TNC];
    __shared__ float wsh[TNC];
    __shared__ float spos[4][TMC];
    __shared__ float sneg[4][TMC];

    const int tid  = threadIdx.x;
    const int warp = tid >> 5;
    const int lane = tid & 31;
    const int g = lane >> 2;          // group id (row within 8)
    const int t = lane & 3;           // thread-in-group (k quad / col pair)
    const int wm = warp >> 2;         // warp M index (0..1)
    const int wn = warp & 3;          // warp N index (0..3)
    const int i0 = blockIdx.x * TMC;
    const int j0 = blockIdx.y * TNC;

    const uint32_t dsm = s2u(dsm_raw);

    // column labels/weights
    {
        int c = tid;
        int yy = y[j0 + c];
        ysh[c] = yy;
        wsh[c] = g_invc[yy];
    }

    // ---- per-thread copy descriptors (6 x 16B per stage) ----
    const char* srcp[6];
    uint32_t    sdst[6];
#pragma unroll
    for (int j = 0; j < 6; ++j) {
        int u   = tid + 256 * j;      // 16B unit index 0..1535
        int row = u >> 2;             // 0..383
        int tt  = u & 3;
        int lr, grow; uint32_t base;
        if (row < TMC) { lr = row;        grow = i0 + lr; base = 0; }
        else           { lr = row - TMC;  grow = j0 + lr; base = A_ST_BYTES; }
        srcp[j] = (const char*)(g_qtf + (size_t)grow * DIM) + tt * 16;
        sdst[j] = base + (uint32_t)lr * 64 + (uint32_t)((tt ^ ((lr >> 1) & 3)) * 16);
    }

    // ---- per-thread fragment read offsets ----
    uint32_t Aoff[4][2], Boff[8];
#pragma unroll
    for (int mt = 0; mt < 4; ++mt) {
#pragma unroll
        for (int h = 0; h < 2; ++h) {
            int r = wm * 64 + mt * 16 + h * 8 + g;
            Aoff[mt][h] = (uint32_t)r * 64 + (uint32_t)((t ^ ((r >> 1) & 3)) * 16);
        }
    }
#pragma unroll
    for (int nt = 0; nt < 8; ++nt) {
        int r = wn * 64 + nt * 8 + g;
        Boff[nt] = A_ST_BYTES + (uint32_t)r * 64 + (uint32_t)((t ^ ((r >> 1) & 3)) * 16);
    }

    float c[4][8][4];
#pragma unroll
    for (int mt = 0; mt < 4; ++mt)
#pragma unroll
        for (int nt = 0; nt < 8; ++nt)
#pragma unroll
            for (int e = 0; e < 4; ++e) c[mt][nt][e] = 0.0f;

    // ---- prologue: stages 0..2 ----
#pragma unroll
    for (int s = 0; s < 3; ++s) {
        uint32_t sb = dsm + s * STAGE_BYTES;
#pragma unroll
        for (int j = 0; j < 6; ++j) cpasync16(sb + sdst[j], srcp[j] + s * 64);
        cp_commit();
    }

    // ---- main loop ----
#pragma unroll 1
    for (int kc = 0; kc < NKS; ++kc) {
        if (kc < NKS - 3) asm volatile("cp.async.wait_group 2;" ::: "memory");
        else              asm volatile("cp.async.wait_group 0;" ::: "memory");
        __syncthreads();

        if (kc + 3 < NKS) {
            int s = kc + 3;
            uint32_t sb = dsm + (s & 3) * STAGE_BYTES;
#pragma unroll
            for (int j = 0; j < 6; ++j) cpasync16(sb + sdst[j], srcp[j] + s * 64);
            cp_commit();
        }

        uint32_t sb = dsm + (kc & 3) * STAGE_BYTES;
        uint32_t a[4][8];
#pragma unroll
        for (int mt = 0; mt < 4; ++mt) {
            lds128(&a[mt][0], sb + Aoff[mt][0]);   // row g:   k quad 4t..4t+3
            lds128(&a[mt][4], sb + Aoff[mt][1]);   // row g+8
        }
#pragma unroll
        for (int nt = 0; nt < 8; ++nt) {
            uint32_t b[4];
            lds128(b, sb + Boff[nt]);
#pragma unroll
            for (int mt = 0; mt < 4; ++mt) {
                MMA_TF32(c[mt][nt], a[mt][0], a[mt][4], a[mt][1], a[mt][5], b[0], b[1]);
                MMA_TF32(c[mt][nt], a[mt][2], a[mt][6], a[mt][3], a[mt][7], b[2], b[3]);
            }
        }
    }

    // ---- fused epilogue: masked exp, in registers ----
    int yrow[8];
#pragma unroll
    for (int mt = 0; mt < 4; ++mt)
#pragma unroll
        for (int h = 0; h < 2; ++h)
            yrow[mt * 2 + h] = y[i0 + wm * 64 + mt * 16 + h * 8 + g];

    float pos[8], neg[8];
#pragma unroll
    for (int e = 0; e < 8; ++e) { pos[e] = 0.0f; neg[e] = 0.0f; }

#pragma unroll
    for (int mt = 0; mt < 4; ++mt) {
        const int gr0 = i0 + wm * 64 + mt * 16 + g;     // rows for c0/c1
        const int gr1 = gr0 + 8;                        // rows for c2/c3
#pragma unroll
        for (int nt = 0; nt < 8; ++nt) {
            const int cl = wn * 64 + nt * 8 + 2 * t;
#pragma unroll
            for (int e = 0; e < 4; ++e) {
                const int col  = cl + (e & 1);
                const int grow = (e < 2) ? gr0 : gr1;
                const int yl   = yrow[mt * 2 + (e >> 1)];
                const int idx  = mt * 2 + (e >> 1);
                float d = c[mt][nt][e];
                float ev = ex2f(d * C2);
                bool nz   = (d != 0.0f);
                bool same = (ysh[col] == yl);
                bool slf  = (j0 + col == grow);
                if (nz & same & !slf) pos[idx] += ev;
                if (nz & !same)       neg[idx] += ev * wsh[col];
            }
        }
    }

    // reduce over the 4 lanes of each group (same rows, different cols)
#pragma unroll
    for (int e = 0; e < 8; ++e) {
        pos[e] += __shfl_xor_sync(0xffffffffu, pos[e], 1);
        pos[e] += __shfl_xor_sync(0xffffffffu, pos[e], 2);
        neg[e] += __shfl_xor_sync(0xffffffffu, neg[e], 1);
        neg[e] += __shfl_xor_sync(0xffffffffu, neg[e], 2);
    }
    if (t == 0) {
#pragma unroll
        for (int mt = 0; mt < 4; ++mt)
#pragma unroll
            for (int h = 0; h < 2; ++h) {
                int r = wm * 64 + mt * 16 + h * 8 + g;
                spos[wn][r] = pos[mt * 2 + h];
                sneg[wn][r] = neg[mt * 2 + h];
            }
    }
    __syncthreads();
    if (tid < TMC) {
        float p = spos[0][tid] + spos[1][tid] + spos[2][tid] + spos[3][tid];
        float n = sneg[0][tid] + sneg[1][tid] + sneg[2][tid] + sneg[3][tid];
        g_pos[blockIdx.y][i0 + tid] = p;
        g_neg[blockIdx.y][i0 + tid] = n;
    }
}

// ---------------- kernel 3: k-positive sims + per-row loss ----------------
__global__ void k_rowloss(const float* __restrict__ q,
                          const float* __restrict__ kv,
                          const int* __restrict__ y) {
    const int warp = threadIdx.x >> 5;
    const int lane = threadIdx.x & 31;
    const int i = blockIdx.x * 8 + warp;

    const float* qi = q + (size_t)i * DIM;
    float esum = 0.0f;
    for (int kk = 0; kk < KPOS; ++kk) {
        const float* kp = kv + ((size_t)i * KPOS + kk) * DIM;
        float acc = 0.0f;
#pragma unroll
        for (int e = 0; e < DIM / 32; ++e)
            acc = fmaf(qi[lane + 32 * e], kp[lane + 32 * e], acc);
#pragma unroll
        for (int off = 16; off > 0; off >>= 1)
            acc += __shfl_down_sync(0xffffffffu, acc, off);
        if (lane == 0) esum += ex2f(acc * C2);
    }
    if (lane == 0) {
        float pt = esum, nt = 0.0f;
#pragma unroll
        for (int sp = 0; sp < NSPL; ++sp) {
            pt += g_pos[sp][i];
            nt += g_neg[sp][i];
        }
        float num = logf(pt);
        float den = logf(nt);
        float cnt = (float)(g_cnt[y[i]] - 1 + KPOS);
        g_loss[i] = -(num - den) / cnt;
    }
}

// ---------------- kernel 4: deterministic mean ----------------
__global__ void k_reduce(float* __restrict__ out) {
    __shared__ float sm[1024];
    float s = 0.0f;
    for (int i = threadIdx.x; i < N_ROWS; i += 1024) s += g_loss[i];
    sm[threadIdx.x] = s;
    __syncthreads();
    for (int st = 512; st > 0; st >>= 1) {
        if (threadIdx.x < st) sm[threadIdx.x] += sm[threadIdx.x + st];
        __syncthreads();
    }
    if (threadIdx.x == 0) out[0] = sm[0] * (1.0f / (float)N_ROWS);
}

// ---------------- launch ----------------
extern "C" void kernel_launch(void* const* d_in, const int* in_sizes, int n_in,
                              void* d_out, int out_size) {
    const float* q  = nullptr;
    const float* kv = nullptr;
    const int*   y  = nullptr;
    for (int i = 0; i < n_in; ++i) {
        long long sz = in_sizes[i];
        if (sz == (long long)N_ROWS * DIM)             q  = (const float*)d_in[i];
        else if (sz == (long long)N_ROWS * KPOS * DIM) kv = (const float*)d_in[i];
        else if (sz == (long long)N_ROWS)              y  = (const int*)d_in[i];
    }
    float* out = (float*)d_out;

    static int configured = 0;
    cudaFuncSetAttribute(k_gram, cudaFuncAttributeMaxDynamicSharedMemorySize, DSM_BYTES);
    (void)configured;

    k_bincount<<<1, 1024>>>(y);
    k_prep<<<(N_ROWS * DIM / 4) / 256, 256>>>(q);
    k_gram<<<dim3(NRB, NSPL), 256, DSM_BYTES>>>(y);
    k_rowloss<<<N_ROWS / 8, 256>>>(q, kv, y);
    k_reduce<<<1, 1024>>>(out);
}

// round 9
// speedup vs baseline: 10.0788x; 1.8277x over previous
#include <cuda_runtime.h>
#include <math.h>
#include <stdint.h>

// ---------------- problem shapes ----------------
#define N_ROWS 8192
#define DIM    512
#define KPOS   8
#define NCLS   1000
#define C2     20.60992915555662f   // log2(e)/0.07

// ---------------- GEMM tiling ----------------
#define TMC 128                    // CTA M tile
#define TNC 256                    // CTA N tile
#define KCH 16                     // K floats per stage
#define NKS (DIM / KCH)            // 32 k-steps
#define NB  (N_ROWS / TNC)         // 32 blocks of 256 (triangular pairing)
#define NMB (N_ROWS / TMC)         // 64 M-blocks of 128
#define NPAIRS (NB * (NB + 1) / 2) // 528
#define NCTAS (2 * NPAIRS)         // 1056
#define A_ST_BYTES (TMC * KCH * 4) // 8192
#define B_ST_BYTES (TNC * KCH * 4) // 16384
#define STAGE_BYTES (A_ST_BYTES + B_ST_BYTES)  // 24576
#define NSTAGES 4
#define DSM_BYTES (NSTAGES * STAGE_BYTES)      // 98304

// ---------------- scratch ----------------
__device__ float g_qtf[N_ROWS * DIM];      // tf32-rounded Q, row-major
__device__ float g_posR[NB][N_ROWS];       // row-sum slots (tile (m,n) -> slot n)
__device__ float g_negR[NB][N_ROWS];
__device__ float g_posC[NMB][N_ROWS];      // col-sum slots (tile (m,n) -> slot m)
__device__ float g_negC[NMB][N_ROWS];
__device__ int   g_cnt[NCLS];
__device__ float g_invc[NCLS];
__device__ float g_loss[N_ROWS];

// ---------------- helpers ----------------
__device__ __forceinline__ uint32_t s2u(const void* p) {
    uint32_t a;
    asm("{ .reg .u64 t; cvta.to.shared.u64 t, %1; cvt.u32.u64 %0, t; }" : "=r"(a) : "l"(p));
    return a;
}
__device__ __forceinline__ void lds128(uint32_t* r, uint32_t a) {
    asm volatile("ld.shared.v4.b32 {%0,%1,%2,%3}, [%4];"
                 : "=r"(r[0]), "=r"(r[1]), "=r"(r[2]), "=r"(r[3]) : "r"(a));
}
__device__ __forceinline__ void cpasync16(uint32_t dst, const void* src) {
    asm volatile("cp.async.cg.shared.global [%0], [%1], 16;" :: "r"(dst), "l"(src) : "memory");
}
__device__ __forceinline__ void cp_commit() {
    asm volatile("cp.async.commit_group;" ::: "memory");
}
__device__ __forceinline__ float ex2f(float x) {
    float r;
    asm("ex2.approx.ftz.f32 %0, %1;" : "=f"(r) : "f"(x));
    return r;
}
#define MMA_TF32(c, a0, a1, a2, a3, b0, b1)                                   \
    asm volatile(                                                             \
        "mma.sync.aligned.m16n8k8.row.col.f32.tf32.tf32.f32 "                 \
        "{%0,%1,%2,%3},{%4,%5,%6,%7},{%8,%9},{%0,%1,%2,%3};"                  \
        : "+f"(c[0]), "+f"(c[1]), "+f"(c[2]), "+f"(c[3])                      \
        : "r"(a0), "r"(a1), "r"(a2), "r"(a3), "r"(b0), "r"(b1))

// ---------------- kernel 0: bincount + reciprocals ----------------
__global__ void k_bincount(const int* __restrict__ y) {
    __shared__ int sc[NCLS];
    for (int c = threadIdx.x; c < NCLS; c += blockDim.x) sc[c] = 0;
    __syncthreads();
    for (int i = threadIdx.x; i < N_ROWS; i += blockDim.x)
        atomicAdd(&sc[y[i]], 1);
    __syncthreads();
    for (int c = threadIdx.x; c < NCLS; c += blockDim.x) {
        int v = sc[c];
        g_cnt[c]  = v;
        g_invc[c] = v > 0 ? 1.0f / (float)v : 0.0f;
    }
}

// ---------------- kernel 1: tf32-round Q (row-major) ----------------
__global__ void k_prep(const float* __restrict__ q) {
    int gid = blockIdx.x * blockDim.x + threadIdx.x;  // one float4
    float4 v = ((const float4*)q)[gid];
    uint32_t o0, o1, o2, o3;
    asm("cvt.rn.tf32.f32 %0, %1;" : "=r"(o0) : "f"(v.x));
    asm("cvt.rn.tf32.f32 %0, %1;" : "=r"(o1) : "f"(v.y));
    asm("cvt.rn.tf32.f32 %0, %1;" : "=r"(o2) : "f"(v.z));
    asm("cvt.rn.tf32.f32 %0, %1;" : "=r"(o3) : "f"(v.w));
    ((uint4*)g_qtf)[gid] = make_uint4(o0, o1, o2, o3);
}

// ---------------- kernel 2: triangular mma.sync tf32 Gram + two-sided epilogue ----------------
// Block pair (bi, bj), bi<=bj over 32 blocks of 256. Each pair -> 2 CTAs (M halves of 128).
// CTA tile: rows [m*128, +128), cols [bj*256, +256). Row sums -> slot bj; col sums -> slot m
// (only when bi != bj). 8 warps = 2(M) x 4(N), warp tile 64x64.
__global__ __launch_bounds__(256, 1)
void k_gram(const int* __restrict__ y) {
    extern __shared__ __align__(16) char dsm_raw[];
    __shared__ int   ysh[TNC];
    __shared__ float wsh[TNC];
    __shared__ float spos[4][TMC];
    __shared__ float sneg[4][TMC];
    __shared__ float scolP[2][TNC];
    __shared__ float scolN[2][TNC];

    const int tid  = threadIdx.x;
    const int warp = tid >> 5;
    const int lane = tid & 31;
    const int g = lane >> 2;          // group id (row within 8)
    const int t = lane & 3;           // thread-in-group (k quad / col pair)
    const int wm = warp >> 2;         // warp M index (0..1)
    const int wn = warp & 3;          // warp N index (0..3)

    // ---- decode triangular pair ----
    int p = blockIdx.x >> 1, h = blockIdx.x & 1;
    int bi = 0, rem = p;
    while (rem >= (NB - bi)) { rem -= (NB - bi); ++bi; }
    const int bj = bi + rem;
    const int m  = 2 * bi + h;            // this CTA's M-block (128 rows)
    const int i0 = m * TMC;
    const int j0 = bj * TNC;
    const bool do_col = (bi != bj);

    const uint32_t dsm = s2u(dsm_raw);

    // column labels/weights
    {
        int c = tid;
        int yy = y[j0 + c];
        ysh[c] = yy;
        wsh[c] = g_invc[yy];
    }

    // ---- per-thread copy descriptors (6 x 16B per stage) ----
    const char* srcp[6];
    uint32_t    sdst[6];
#pragma unroll
    for (int j = 0; j < 6; ++j) {
        int u   = tid + 256 * j;      // 16B unit index 0..1535
        int row = u >> 2;             // 0..383
        int tt  = u & 3;
        int lr, grow; uint32_t base;
        if (row < TMC) { lr = row;        grow = i0 + lr; base = 0; }
        else           { lr = row - TMC;  grow = j0 + lr; base = A_ST_BYTES; }
        srcp[j] = (const char*)(g_qtf + (size_t)grow * DIM) + tt * 16;
        sdst[j] = base + (uint32_t)lr * 64 + (uint32_t)((tt ^ ((lr >> 1) & 3)) * 16);
    }

    // ---- per-thread fragment read offsets ----
    uint32_t Aoff[4][2], Boff[8];
#pragma unroll
    for (int mt = 0; mt < 4; ++mt) {
#pragma unroll
        for (int hh = 0; hh < 2; ++hh) {
            int r = wm * 64 + mt * 16 + hh * 8 + g;
            Aoff[mt][hh] = (uint32_t)r * 64 + (uint32_t)((t ^ ((r >> 1) & 3)) * 16);
        }
    }
#pragma unroll
    for (int nt = 0; nt < 8; ++nt) {
        int r = wn * 64 + nt * 8 + g;
        Boff[nt] = A_ST_BYTES + (uint32_t)r * 64 + (uint32_t)((t ^ ((r >> 1) & 3)) * 16);
    }

    float c[4][8][4];
#pragma unroll
    for (int mt = 0; mt < 4; ++mt)
#pragma unroll
        for (int nt = 0; nt < 8; ++nt)
#pragma unroll
            for (int e = 0; e < 4; ++e) c[mt][nt][e] = 0.0f;

    // ---- prologue: stages 0..2 ----
#pragma unroll
    for (int s = 0; s < 3; ++s) {
        uint32_t sb = dsm + s * STAGE_BYTES;
#pragma unroll
        for (int j = 0; j < 6; ++j) cpasync16(sb + sdst[j], srcp[j] + s * 64);
        cp_commit();
    }

    // ---- main loop ----
#pragma unroll 1
    for (int kc = 0; kc < NKS; ++kc) {
        if (kc < NKS - 3) asm volatile("cp.async.wait_group 2;" ::: "memory");
        else              asm volatile("cp.async.wait_group 0;" ::: "memory");
        __syncthreads();

        if (kc + 3 < NKS) {
            int s = kc + 3;
            uint32_t sb = dsm + (s & 3) * STAGE_BYTES;
#pragma unroll
            for (int j = 0; j < 6; ++j) cpasync16(sb + sdst[j], srcp[j] + s * 64);
            cp_commit();
        }

        uint32_t sb = dsm + (kc & 3) * STAGE_BYTES;
        uint32_t a[4][8];
#pragma unroll
        for (int mt = 0; mt < 4; ++mt) {
            lds128(&a[mt][0], sb + Aoff[mt][0]);   // row g:   k quad 4t..4t+3
            lds128(&a[mt][4], sb + Aoff[mt][1]);   // row g+8
        }
#pragma unroll
        for (int nt = 0; nt < 8; ++nt) {
            uint32_t b[4];
            lds128(b, sb + Boff[nt]);
#pragma unroll
            for (int mt = 0; mt < 4; ++mt) {
                MMA_TF32(c[mt][nt], a[mt][0], a[mt][4], a[mt][1], a[mt][5], b[0], b[1]);
                MMA_TF32(c[mt][nt], a[mt][2], a[mt][6], a[mt][3], a[mt][7], b[2], b[3]);
            }
        }
    }

    // ---- fused two-sided epilogue ----
    int   yrow[8];
    float winv[8];
#pragma unroll
    for (int mt = 0; mt < 4; ++mt)
#pragma unroll
        for (int hh = 0; hh < 2; ++hh) {
            int yy = y[i0 + wm * 64 + mt * 16 + hh * 8 + g];
            yrow[mt * 2 + hh] = yy;
            winv[mt * 2 + hh] = g_invc[yy];
        }

    float pos[8], neg[8];
    float colp[16], coln[16];
#pragma unroll
    for (int e = 0; e < 8; ++e)  { pos[e] = 0.0f;  neg[e] = 0.0f; }
#pragma unroll
    for (int e = 0; e < 16; ++e) { colp[e] = 0.0f; coln[e] = 0.0f; }

#pragma unroll
    for (int mt = 0; mt < 4; ++mt) {
        const int gr0 = i0 + wm * 64 + mt * 16 + g;     // rows for c0/c1
        const int gr1 = gr0 + 8;                        // rows for c2/c3
#pragma unroll
        for (int nt = 0; nt < 8; ++nt) {
            const int cl = wn * 64 + nt * 8 + 2 * t;
#pragma unroll
            for (int e = 0; e < 4; ++e) {
                const int col  = cl + (e & 1);
                const int grow = (e < 2) ? gr0 : gr1;
                const int idx  = mt * 2 + (e >> 1);
                const int ci   = nt * 2 + (e & 1);
                float d = c[mt][nt][e];
                float ev = ex2f(d * C2);
                bool nz   = (d != 0.0f);
                bool same = (ysh[col] == yrow[idx]);
                bool slf  = (j0 + col == grow);
                if (nz & same & !slf) pos[idx] += ev;
                if (nz & !same)       neg[idx] += ev * wsh[col];
                // transposed contribution (rows of bj get sums over this CTA's rows)
                if (nz & same)        colp[ci] += ev;              // jg != grow when do_col
                if (nz & !same)       coln[ci] += ev * winv[idx];
            }
        }
    }

    // row reduce over the 4 lanes of each group (t axis)
#pragma unroll
    for (int e = 0; e < 8; ++e) {
        pos[e] += __shfl_xor_sync(0xffffffffu, pos[e], 1);
        pos[e] += __shfl_xor_sync(0xffffffffu, pos[e], 2);
        neg[e] += __shfl_xor_sync(0xffffffffu, neg[e], 1);
        neg[e] += __shfl_xor_sync(0xffffffffu, neg[e], 2);
    }
    if (t == 0) {
#pragma unroll
        for (int mt = 0; mt < 4; ++mt)
#pragma unroll
            for (int hh = 0; hh < 2; ++hh) {
                int r = wm * 64 + mt * 16 + hh * 8 + g;
                spos[wn][r] = pos[mt * 2 + hh];
                sneg[wn][r] = neg[mt * 2 + hh];
            }
    }

    // col reduce over the 8 groups (g axis)
#pragma unroll
    for (int e = 0; e < 16; ++e) {
        colp[e] += __shfl_xor_sync(0xffffffffu, colp[e], 4);
        colp[e] += __shfl_xor_sync(0xffffffffu, colp[e], 8);
        colp[e] += __shfl_xor_sync(0xffffffffu, colp[e], 16);
        coln[e] += __shfl_xor_sync(0xffffffffu, coln[e], 4);
        coln[e] += __shfl_xor_sync(0xffffffffu, coln[e], 8);
        coln[e] += __shfl_xor_sync(0xffffffffu, coln[e], 16);
    }
    if (g == 0) {  // lanes 0..3 hold full g-sums; each (nt, e01) is a distinct col
#pragma unroll
        for (int nt = 0; nt < 8; ++nt)
#pragma unroll
            for (int e01 = 0; e01 < 2; ++e01) {
                int col = wn * 64 + nt * 8 + 2 * t + e01;
                // accumulate across wm warps: first wm writes, second adds
                if (wm == 0) { scolP[0][col] = colp[nt * 2 + e01]; scolN[0][col] = coln[nt * 2 + e01]; }
                else         { scolP[1][col] = colp[nt * 2 + e01]; scolN[1][col] = coln[nt * 2 + e01]; }
            }
    }
    __syncthreads();
    if (tid < TMC) {
        float pp = spos[0][tid] + spos[1][tid] + spos[2][tid] + spos[3][tid];
        float nn = sneg[0][tid] + sneg[1][tid] + sneg[2][tid] + sneg[3][tid];
        g_posR[bj][i0 + tid] = pp;
        g_negR[bj][i0 + tid] = nn;
    }
    if (do_col) {
        int cc = tid;   // 0..255
        float pp = scolP[0][cc] + scolP[1][cc];
        float nn = scolN[0][cc] + scolN[1][cc];
        g_posC[m][j0 + cc] = pp;
        g_negC[m][j0 + cc] = nn;
    }
}

// ---------------- kernel 3: k-positive sims + per-row loss ----------------
__global__ void k_rowloss(const float* __restrict__ q,
                          const float* __restrict__ kv,
                          const int* __restrict__ y) {
    const int warp = threadIdx.x >> 5;
    const int lane = threadIdx.x & 31;
    const int i = blockIdx.x * 8 + warp;

    const float* qi = q + (size_t)i * DIM;
    float esum = 0.0f;
    for (int kk = 0; kk < KPOS; ++kk) {
        const float* kp = kv + ((size_t)i * KPOS + kk) * DIM;
        float acc = 0.0f;
#pragma unroll
        for (int e = 0; e < DIM / 32; ++e)
            acc = fmaf(qi[lane + 32 * e], kp[lane + 32 * e], acc);
#pragma unroll
        for (int off = 16; off > 0; off >>= 1)
            acc += __shfl_down_sync(0xffffffffu, acc, off);
        if (lane == 0) esum += ex2f(acc * C2);
    }
    if (lane == 0) {
        const int b = i >> 8;                 // 256-block of this row
        float pt = esum, nt = 0.0f;
        for (int sp = b; sp < NB; ++sp) {     // row-sum slots
            pt += g_posR[sp][i];
            nt += g_negR[sp][i];
        }
        for (int mm = 0; mm < 2 * b; ++mm) {  // col-sum slots
            pt += g_posC[mm][i];
            nt += g_negC[mm][i];
        }
        float num = logf(pt);
        float den = logf(nt);
        float cnt = (float)(g_cnt[y[i]] - 1 + KPOS);
        g_loss[i] = -(num - den) / cnt;
    }
}

// ---------------- kernel 4: deterministic mean ----------------
__global__ void k_reduce(float* __restrict__ out) {
    __shared__ float sm[1024];
    float s = 0.0f;
    for (int i = threadIdx.x; i < N_ROWS; i += 1024) s += g_loss[i];
    sm[threadIdx.x] = s;
    __syncthreads();
    for (int st = 512; st > 0; st >>= 1) {
        if (threadIdx.x < st) sm[threadIdx.x] += sm[threadIdx.x + st];
        __syncthreads();
    }
    if (threadIdx.x == 0) out[0] = sm[0] * (1.0f / (float)N_ROWS);
}

// ---------------- launch ----------------
extern "C" void kernel_launch(void* const* d_in, const int* in_sizes, int n_in,
                              void* d_out, int out_size) {
    const float* q  = nullptr;
    const float* kv = nullptr;
    const int*   y  = nullptr;
    for (int i = 0; i < n_in; ++i) {
        long long sz = in_sizes[i];
        if (sz == (long long)N_ROWS * DIM)             q  = (const float*)d_in[i];
        else if (sz == (long long)N_ROWS * KPOS * DIM) kv = (const float*)d_in[i];
        else if (sz == (long long)N_ROWS)              y  = (const int*)d_in[i];
    }
    float* out = (float*)d_out;

    cudaFuncSetAttribute(k_gram, cudaFuncAttributeMaxDynamicSharedMemorySize, DSM_BYTES);

    k_bincount<<<1, 1024>>>(y);
    k_prep<<<(N_ROWS * DIM / 4) / 256, 256>>>(q);
    k_gram<<<NCTAS, 256, DSM_BYTES>>>(y);
    k_rowloss<<<N_ROWS / 8, 256>>>(q, kv, y);
    k_reduce<<<1, 1024>>>(out);
}

// round 10
// speedup vs baseline: 10.9699x; 1.0884x over previous
#include <cuda_runtime.h>
#include <cuda_fp16.h>
#include <math.h>
#include <stdint.h>

// ---------------- problem shapes ----------------
#define N_ROWS 8192
#define DIM    512
#define KPOS   8
#define NCLS   1000
#define C2     20.60992915555662f   // log2(e)/0.07

// ---------------- GEMM tiling ----------------
#define TMC 128                    // CTA M tile
#define TNC 256                    // CTA N tile
#define KCH 32                     // K halves per stage (two m16n8k16 sub-steps)
#define NKS (DIM / KCH)            // 16 k-steps
#define NB  (N_ROWS / TNC)         // 32 blocks of 256 (triangular pairing)
#define NMB (N_ROWS / TMC)         // 64 M-blocks of 128
#define NPAIRS (NB * (NB + 1) / 2) // 528
#define NCTAS (2 * NPAIRS)         // 1056
#define A_ST_BYTES (TMC * KCH * 2) // 8192
#define B_ST_BYTES (TNC * KCH * 2) // 16384
#define STAGE_BYTES (A_ST_BYTES + B_ST_BYTES)  // 24576
#define NSTAGES 4
#define DSM_BYTES (NSTAGES * STAGE_BYTES)      // 98304

// ---------------- scratch ----------------
__device__ __align__(16) __half g_qh[N_ROWS * DIM];  // fp16 Q, row-major
__device__ float g_posR[NB][N_ROWS];       // row-sum slots (tile (m,n) -> slot n)
__device__ float g_negR[NB][N_ROWS];
__device__ float g_posC[NMB][N_ROWS];      // col-sum slots (tile (m,n) -> slot m)
__device__ float g_negC[NMB][N_ROWS];
__device__ int   g_cnt[NCLS];
__device__ float g_invc[NCLS];
__device__ float g_loss[N_ROWS];

// ---------------- helpers ----------------
__device__ __forceinline__ uint32_t s2u(const void* p) {
    uint32_t a;
    asm("{ .reg .u64 t; cvta.to.shared.u64 t, %1; cvt.u32.u64 %0, t; }" : "=r"(a) : "l"(p));
    return a;
}
__device__ __forceinline__ void lds128(uint32_t* r, uint32_t a) {
    asm volatile("ld.shared.v4.b32 {%0,%1,%2,%3}, [%4];"
                 : "=r"(r[0]), "=r"(r[1]), "=r"(r[2]), "=r"(r[3]) : "r"(a));
}
__device__ __forceinline__ void cpasync16(uint32_t dst, const void* src) {
    asm volatile("cp.async.cg.shared.global [%0], [%1], 16;" :: "r"(dst), "l"(src) : "memory");
}
__device__ __forceinline__ void cp_commit() {
    asm volatile("cp.async.commit_group;" ::: "memory");
}
__device__ __forceinline__ float ex2f(float x) {
    float r;
    asm("ex2.approx.ftz.f32 %0, %1;" : "=f"(r) : "f"(x));
    return r;
}
// fp16 mma, fp32 accum. k-slot permutation: sub-mma uses contiguous 16B row chunks.
#define MMA_F16(c, a0, a1, a2, a3, b0, b1)                                    \
    asm volatile(                                                             \
        "mma.sync.aligned.m16n8k16.row.col.f32.f16.f16.f32 "                  \
        "{%0,%1,%2,%3},{%4,%5,%6,%7},{%8,%9},{%0,%1,%2,%3};"                  \
        : "+f"(c[0]), "+f"(c[1]), "+f"(c[2]), "+f"(c[3])                      \
        : "r"(a0), "r"(a1), "r"(a2), "r"(a3), "r"(b0), "r"(b1))

// ---------------- kernel 0: bincount + reciprocals ----------------
__global__ void k_bincount(const int* __restrict__ y) {
    __shared__ int sc[NCLS];
    for (int c = threadIdx.x; c < NCLS; c += blockDim.x) sc[c] = 0;
    __syncthreads();
    for (int i = threadIdx.x; i < N_ROWS; i += blockDim.x)
        atomicAdd(&sc[y[i]], 1);
    __syncthreads();
    for (int c = threadIdx.x; c < NCLS; c += blockDim.x) {
        int v = sc[c];
        g_cnt[c]  = v;
        g_invc[c] = v > 0 ? 1.0f / (float)v : 0.0f;
    }
}

// ---------------- kernel 1: fp16-convert Q (row-major) ----------------
__global__ void k_prep(const float* __restrict__ q) {
    int gid = blockIdx.x * blockDim.x + threadIdx.x;  // 8 floats each
    const float4* q4 = (const float4*)q;
    float4 v0 = q4[gid * 2 + 0];
    float4 v1 = q4[gid * 2 + 1];
    __half2 h0 = __float22half2_rn(make_float2(v0.x, v0.y));
    __half2 h1 = __float22half2_rn(make_float2(v0.z, v0.w));
    __half2 h2 = __float22half2_rn(make_float2(v1.x, v1.y));
    __half2 h3 = __float22half2_rn(make_float2(v1.z, v1.w));
    uint4 o;
    o.x = *(uint32_t*)&h0; o.y = *(uint32_t*)&h1;
    o.z = *(uint32_t*)&h2; o.w = *(uint32_t*)&h3;
    ((uint4*)g_qh)[gid] = o;
}

// ---------------- kernel 2: triangular fp16 mma Gram + two-sided epilogue ----------------
// Block pair (bi, bj), bi<=bj over 32 blocks of 256. Each pair -> 2 CTAs (M halves of 128).
// CTA tile: rows [m*128, +128), cols [bj*256, +256). Row sums -> slot bj; col sums -> slot m.
// 8 warps = 2(M) x 4(N), warp tile 64x64.
__global__ __launch_bounds__(256, 1)
void k_gram(const int* __restrict__ y) {
    extern __shared__ __align__(16) char dsm_raw[];
    __shared__ int   ysh[TNC];
    __shared__ float wsh[TNC];
    __shared__ float spos[4][TMC];
    __shared__ float sneg[4][TMC];
    __shared__ float scolP[2][TNC];
    __shared__ float scolN[2][TNC];

    const int tid  = threadIdx.x;
    const int warp = tid >> 5;
    const int lane = tid & 31;
    const int g = lane >> 2;          // group id (row within 8)
    const int t = lane & 3;           // thread-in-group (16B row chunk)
    const int wm = warp >> 2;         // warp M index (0..1)
    const int wn = warp & 3;          // warp N index (0..3)

    // ---- decode triangular pair ----
    int p = blockIdx.x >> 1, h = blockIdx.x & 1;
    int bi = 0, rem = p;
    while (rem >= (NB - bi)) { rem -= (NB - bi); ++bi; }
    const int bj = bi + rem;
    const int m  = 2 * bi + h;            // this CTA's M-block (128 rows)
    const int i0 = m * TMC;
    const int j0 = bj * TNC;
    const bool do_col = (bi != bj);

    const uint32_t dsm = s2u(dsm_raw);

    // column labels/weights
    {
        int c = tid;
        int yy = y[j0 + c];
        ysh[c] = yy;
        wsh[c] = g_invc[yy];
    }

    // ---- per-thread copy descriptors (6 x 16B per stage) ----
    const char* srcp[6];
    uint32_t    sdst[6];
#pragma unroll
    for (int j = 0; j < 6; ++j) {
        int u   = tid + 256 * j;      // 16B unit index 0..1535
        int row = u >> 2;             // 0..383
        int tt  = u & 3;
        int lr, grow; uint32_t base;
        if (row < TMC) { lr = row;        grow = i0 + lr; base = 0; }
        else           { lr = row - TMC;  grow = j0 + lr; base = A_ST_BYTES; }
        srcp[j] = (const char*)(g_qh + (size_t)grow * DIM) + tt * 16;
        sdst[j] = base + (uint32_t)lr * 64 + (uint32_t)((tt ^ ((lr >> 1) & 3)) * 16);
    }

    // ---- per-thread fragment read offsets (64B rows) ----
    uint32_t Aoff[4][2], Boff[8];
#pragma unroll
    for (int mt = 0; mt < 4; ++mt) {
#pragma unroll
        for (int hh = 0; hh < 2; ++hh) {
            int r = wm * 64 + mt * 16 + hh * 8 + g;
            Aoff[mt][hh] = (uint32_t)r * 64 + (uint32_t)((t ^ ((r >> 1) & 3)) * 16);
        }
    }
#pragma unroll
    for (int nt = 0; nt < 8; ++nt) {
        int r = wn * 64 + nt * 8 + g;
        Boff[nt] = A_ST_BYTES + (uint32_t)r * 64 + (uint32_t)((t ^ ((r >> 1) & 3)) * 16);
    }

    float c[4][8][4];
#pragma unroll
    for (int mt = 0; mt < 4; ++mt)
#pragma unroll
        for (int nt = 0; nt < 8; ++nt)
#pragma unroll
            for (int e = 0; e < 4; ++e) c[mt][nt][e] = 0.0f;

    // ---- prologue: stages 0..2 ----
#pragma unroll
    for (int s = 0; s < 3; ++s) {
        uint32_t sb = dsm + s * STAGE_BYTES;
#pragma unroll
        for (int j = 0; j < 6; ++j) cpasync16(sb + sdst[j], srcp[j] + s * 64);
        cp_commit();
    }

    // ---- main loop (16 k-steps of 32 halves) ----
#pragma unroll 1
    for (int kc = 0; kc < NKS; ++kc) {
        if (kc < NKS - 3) asm volatile("cp.async.wait_group 2;" ::: "memory");
        else              asm volatile("cp.async.wait_group 0;" ::: "memory");
        __syncthreads();

        if (kc + 3 < NKS) {
            int s = kc + 3;
            uint32_t sb = dsm + (s & 3) * STAGE_BYTES;
#pragma unroll
            for (int j = 0; j < 6; ++j) cpasync16(sb + sdst[j], srcp[j] + s * 64);
            cp_commit();
        }

        uint32_t sb = dsm + (kc & 3) * STAGE_BYTES;
        uint32_t a[4][8];
#pragma unroll
        for (int mt = 0; mt < 4; ++mt) {
            lds128(&a[mt][0], sb + Aoff[mt][0]);   // row g:   halves 8t..8t+7
            lds128(&a[mt][4], sb + Aoff[mt][1]);   // row g+8
        }
#pragma unroll
        for (int nt = 0; nt < 8; ++nt) {
            uint32_t b[4];
            lds128(b, sb + Boff[nt]);
#pragma unroll
            for (int mt = 0; mt < 4; ++mt) {
                // sub-mma 0: halves 0..3 of chunk; sub-mma 1: halves 4..7
                MMA_F16(c[mt][nt], a[mt][0], a[mt][4], a[mt][1], a[mt][5], b[0], b[1]);
                MMA_F16(c[mt][nt], a[mt][2], a[mt][6], a[mt][3], a[mt][7], b[2], b[3]);
            }
        }
    }

    // ---- fused two-sided epilogue ----
    int   yrow[8];
    float winv[8];
#pragma unroll
    for (int mt = 0; mt < 4; ++mt)
#pragma unroll
        for (int hh = 0; hh < 2; ++hh) {
            int yy = y[i0 + wm * 64 + mt * 16 + hh * 8 + g];
            yrow[mt * 2 + hh] = yy;
            winv[mt * 2 + hh] = g_invc[yy];
        }

    float pos[8], neg[8];
    float colp[16], coln[16];
#pragma unroll
    for (int e = 0; e < 8; ++e)  { pos[e] = 0.0f;  neg[e] = 0.0f; }
#pragma unroll
    for (int e = 0; e < 16; ++e) { colp[e] = 0.0f; coln[e] = 0.0f; }

#pragma unroll
    for (int mt = 0; mt < 4; ++mt) {
        const int gr0 = i0 + wm * 64 + mt * 16 + g;     // rows for c0/c1
        const int gr1 = gr0 + 8;                        // rows for c2/c3
#pragma unroll
        for (int nt = 0; nt < 8; ++nt) {
            const int cl = wn * 64 + nt * 8 + 2 * t;
#pragma unroll
            for (int e = 0; e < 4; ++e) {
                const int col  = cl + (e & 1);
                const int grow = (e < 2) ? gr0 : gr1;
                const int idx  = mt * 2 + (e >> 1);
                const int ci   = nt * 2 + (e & 1);
                float d = c[mt][nt][e];
                float ev = ex2f(d * C2);
                bool nz   = (d != 0.0f);
                bool same = (ysh[col] == yrow[idx]);
                bool slf  = (j0 + col == grow);
                if (nz & same & !slf) pos[idx] += ev;
                if (nz & !same)       neg[idx] += ev * wsh[col];
                // transposed contribution (rows of bj get sums over this CTA's rows)
                if (nz & same)        colp[ci] += ev;
                if (nz & !same)       coln[ci] += ev * winv[idx];
            }
        }
    }

    // row reduce over the 4 lanes of each group (t axis)
#pragma unroll
    for (int e = 0; e < 8; ++e) {
        pos[e] += __shfl_xor_sync(0xffffffffu, pos[e], 1);
        pos[e] += __shfl_xor_sync(0xffffffffu, pos[e], 2);
        neg[e] += __shfl_xor_sync(0xffffffffu, neg[e], 1);
        neg[e] += __shfl_xor_sync(0xffffffffu, neg[e], 2);
    }
    if (t == 0) {
#pragma unroll
        for (int mt = 0; mt < 4; ++mt)
#pragma unroll
            for (int hh = 0; hh < 2; ++hh) {
                int r = wm * 64 + mt * 16 + hh * 8 + g;
                spos[wn][r] = pos[mt * 2 + hh];
                sneg[wn][r] = neg[mt * 2 + hh];
            }
    }

    // col reduce over the 8 groups (g axis)
#pragma unroll
    for (int e = 0; e < 16; ++e) {
        colp[e] += __shfl_xor_sync(0xffffffffu, colp[e], 4);
        colp[e] += __shfl_xor_sync(0xffffffffu, colp[e], 8);
        colp[e] += __shfl_xor_sync(0xffffffffu, colp[e], 16);
        coln[e] += __shfl_xor_sync(0xffffffffu, coln[e], 4);
        coln[e] += __shfl_xor_sync(0xffffffffu, coln[e], 8);
        coln[e] += __shfl_xor_sync(0xffffffffu, coln[e], 16);
    }
    if (g == 0) {
#pragma unroll
        for (int nt = 0; nt < 8; ++nt)
#pragma unroll
            for (int e01 = 0; e01 < 2; ++e01) {
                int col = wn * 64 + nt * 8 + 2 * t + e01;
                if (wm == 0) { scolP[0][col] = colp[nt * 2 + e01]; scolN[0][col] = coln[nt * 2 + e01]; }
                else         { scolP[1][col] = colp[nt * 2 + e01]; scolN[1][col] = coln[nt * 2 + e01]; }
            }
    }
    __syncthreads();
    if (tid < TMC) {
        float pp = spos[0][tid] + spos[1][tid] + spos[2][tid] + spos[3][tid];
        float nn = sneg[0][tid] + sneg[1][tid] + sneg[2][tid] + sneg[3][tid];
        g_posR[bj][i0 + tid] = pp;
        g_negR[bj][i0 + tid] = nn;
    }
    if (do_col) {
        int cc = tid;
        float pp = scolP[0][cc] + scolP[1][cc];
        float nn = scolN[0][cc] + scolN[1][cc];
        g_posC[m][j0 + cc] = pp;
        g_negC[m][j0 + cc] = nn;
    }
}

// ---------------- kernel 3: k-positive sims + per-row loss ----------------
__global__ void k_rowloss(const float* __restrict__ q,
                          const float* __restrict__ kv,
                          const int* __restrict__ y) {
    const int warp = threadIdx.x >> 5;
    const int lane = threadIdx.x & 31;
    const int i = blockIdx.x * 8 + warp;

    const float4* qi = (const float4*)(q + (size_t)i * DIM);
    float esum = 0.0f;
    for (int kk = 0; kk < KPOS; ++kk) {
        const float4* kp = (const float4*)(kv + ((size_t)i * KPOS + kk) * DIM);
        float acc = 0.0f;
#pragma unroll
        for (int e = 0; e < DIM / 128; ++e) {
            float4 a = qi[lane + 32 * e];
            float4 b = kp[lane + 32 * e];
            acc = fmaf(a.x, b.x, acc);
            acc = fmaf(a.y, b.y, acc);
            acc = fmaf(a.z, b.z, acc);
            acc = fmaf(a.w, b.w, acc);
        }
#pragma unroll
        for (int off = 16; off > 0; off >>= 1)
            acc += __shfl_down_sync(0xffffffffu, acc, off);
        if (lane == 0) esum += ex2f(acc * C2);
    }

    // parallel slot gather (fixed order -> deterministic)
    const int b = i >> 8;
    float pt = 0.0f, nt = 0.0f;
    if (lane < NB - b)     { pt += g_posR[b + lane][i];   nt += g_negR[b + lane][i]; }
    if (lane < 2 * b)      { pt += g_posC[lane][i];       nt += g_negC[lane][i]; }
    if (lane + 32 < 2 * b) { pt += g_posC[lane + 32][i];  nt += g_negC[lane + 32][i]; }
#pragma unroll
    for (int off = 16; off > 0; off >>= 1) {
        pt += __shfl_down_sync(0xffffffffu, pt, off);
        nt += __shfl_down_sync(0xffffffffu, nt, off);
    }
    if (lane == 0) {
        pt += esum;
        float num = logf(pt);
        float den = logf(nt);
        float cnt = (float)(g_cnt[y[i]] - 1 + KPOS);
        g_loss[i] = -(num - den) / cnt;
    }
}

// ---------------- kernel 4: deterministic mean ----------------
__global__ void k_reduce(float* __restrict__ out) {
    __shared__ float sm[1024];
    const float4* l4 = (const float4*)g_loss;
    float4 v0 = l4[threadIdx.x];
    float4 v1 = l4[threadIdx.x + 1024];
    float s = ((v0.x + v0.y) + (v0.z + v0.w)) + ((v1.x + v1.y) + (v1.z + v1.w));
    sm[threadIdx.x] = s;
    __syncthreads();
    for (int st = 512; st > 0; st >>= 1) {
        if (threadIdx.x < st) sm[threadIdx.x] += sm[threadIdx.x + st];
        __syncthreads();
    }
    if (threadIdx.x == 0) out[0] = sm[0] * (1.0f / (float)N_ROWS);
}

// ---------------- launch ----------------
extern "C" void kernel_launch(void* const* d_in, const int* in_sizes, int n_in,
                              void* d_out, int out_size) {
    const float* q  = nullptr;
    const float* kv = nullptr;
    const int*   y  = nullptr;
    for (int i = 0; i < n_in; ++i) {
        long long sz = in_sizes[i];
        if (sz == (long long)N_ROWS * DIM)             q  = (const float*)d_in[i];
        else if (sz == (long long)N_ROWS * KPOS * DIM) kv = (const float*)d_in[i];
        else if (sz == (long long)N_ROWS)              y  = (const int*)d_in[i];
    }
    float* out = (float*)d_out;

    cudaFuncSetAttribute(k_gram, cudaFuncAttributeMaxDynamicSharedMemorySize, DSM_BYTES);

    k_bincount<<<1, 1024>>>(y);
    k_prep<<<(N_ROWS * DIM / 8) / 256, 256>>>(q);
    k_gram<<<NCTAS, 256, DSM_BYTES>>>(y);
    k_rowloss<<<N_ROWS / 8, 256>>>(q, kv, y);
    k_reduce<<<1, 1024>>>(out);
}

// round 11
// speedup vs baseline: 18.2445x; 1.6631x over previous
#include <cuda_runtime.h>
#include <cuda_fp16.h>
#include <math.h>
#include <stdint.h>

// ---------------- problem shapes ----------------
#define N_ROWS 8192
#define DIM    512
#define KPOS   8
#define NCLS   1000
#define C2     20.60992915555662f   // log2(e)/0.07

// ---------------- GEMM tiling ----------------
#define TMC 128                    // CTA M tile
#define TNC 128                    // CTA N tile
#define KCH 32                     // K halves per stage (two m16n8k16 sub-steps)
#define NKS (DIM / KCH)            // 16 k-steps
#define NB  (N_ROWS / 128)         // 64 blocks of 128 (triangular pairing)
#define NPAIRS (NB * (NB + 1) / 2) // 2080 CTAs
#define A_ST_BYTES (TMC * KCH * 2) // 8192
#define B_ST_BYTES (TNC * KCH * 2) // 8192
#define STAGE_BYTES (A_ST_BYTES + B_ST_BYTES)  // 16384
#define NSTAGES 4
#define DSM_BYTES (NSTAGES * STAGE_BYTES)      // 65536

// ---------------- scratch ----------------
__device__ __align__(16) __half g_qh[N_ROWS * DIM];  // fp16 Q, row-major
__device__ float g_posR[NB][N_ROWS];       // tile (bi,bj) row sums -> slot bj
__device__ float g_negR[NB][N_ROWS];
__device__ float g_posC[NB][N_ROWS];       // tile (bi,bj) col sums -> slot bi (bi!=bj)
__device__ float g_negC[NB][N_ROWS];
__device__ int   g_cnt[NCLS];
__device__ float g_invc[NCLS];
__device__ float g_loss[N_ROWS];

// ---------------- helpers ----------------
__device__ __forceinline__ uint32_t s2u(const void* p) {
    uint32_t a;
    asm("{ .reg .u64 t; cvta.to.shared.u64 t, %1; cvt.u32.u64 %0, t; }" : "=r"(a) : "l"(p));
    return a;
}
__device__ __forceinline__ void lds128(uint32_t* r, uint32_t a) {
    asm volatile("ld.shared.v4.b32 {%0,%1,%2,%3}, [%4];"
                 : "=r"(r[0]), "=r"(r[1]), "=r"(r[2]), "=r"(r[3]) : "r"(a));
}
__device__ __forceinline__ void cpasync16(uint32_t dst, const void* src) {
    asm volatile("cp.async.cg.shared.global [%0], [%1], 16;" :: "r"(dst), "l"(src) : "memory");
}
__device__ __forceinline__ void cp_commit() {
    asm volatile("cp.async.commit_group;" ::: "memory");
}
__device__ __forceinline__ float ex2f(float x) {
    float r;
    asm("ex2.approx.ftz.f32 %0, %1;" : "=f"(r) : "f"(x));
    return r;
}
// fp16 mma, fp32 accum. k-slot permutation: sub-mma uses contiguous 16B row chunks.
#define MMA_F16(c, a0, a1, a2, a3, b0, b1)                                    \
    asm volatile(                                                             \
        "mma.sync.aligned.m16n8k16.row.col.f32.f16.f16.f32 "                  \
        "{%0,%1,%2,%3},{%4,%5,%6,%7},{%8,%9},{%0,%1,%2,%3};"                  \
        : "+f"(c[0]), "+f"(c[1]), "+f"(c[2]), "+f"(c[3])                      \
        : "r"(a0), "r"(a1), "r"(a2), "r"(a3), "r"(b0), "r"(b1))

// ---------------- kernel 0: bincount + reciprocals ----------------
__global__ void k_bincount(const int* __restrict__ y) {
    __shared__ int sc[NCLS];
    for (int c = threadIdx.x; c < NCLS; c += blockDim.x) sc[c] = 0;
    __syncthreads();
    for (int i = threadIdx.x; i < N_ROWS; i += blockDim.x)
        atomicAdd(&sc[y[i]], 1);
    __syncthreads();
    for (int c = threadIdx.x; c < NCLS; c += blockDim.x) {
        int v = sc[c];
        g_cnt[c]  = v;
        g_invc[c] = v > 0 ? 1.0f / (float)v : 0.0f;
    }
}

// ---------------- kernel 1: fp16-convert Q (row-major) ----------------
__global__ void k_prep(const float* __restrict__ q) {
    int gid = blockIdx.x * blockDim.x + threadIdx.x;  // 8 floats each
    const float4* q4 = (const float4*)q;
    float4 v0 = q4[gid * 2 + 0];
    float4 v1 = q4[gid * 2 + 1];
    __half2 h0 = __float22half2_rn(make_float2(v0.x, v0.y));
    __half2 h1 = __float22half2_rn(make_float2(v0.z, v0.w));
    __half2 h2 = __float22half2_rn(make_float2(v1.x, v1.y));
    __half2 h3 = __float22half2_rn(make_float2(v1.z, v1.w));
    uint4 o;
    o.x = *(uint32_t*)&h0; o.y = *(uint32_t*)&h1;
    o.z = *(uint32_t*)&h2; o.w = *(uint32_t*)&h3;
    ((uint4*)g_qh)[gid] = o;
}

// ---------------- kernel 2: triangular fp16 mma Gram + two-sided epilogue ----------------
// Pair (bi, bj), bi<=bj over 64 blocks of 128. CTA tile: rows [bi*128, +128),
// cols [bj*128, +128). Row sums -> slot bj; col sums -> slot bi (bi!=bj).
// 8 warps = 4(M) x 2(N), warp tile 32x64. 2 CTAs/SM.
__global__ __launch_bounds__(256, 2)
void k_gram(const int* __restrict__ y) {
    extern __shared__ __align__(16) char dsm_raw[];
    __shared__ int   ysh[TNC];
    __shared__ float wsh[TNC];
    __shared__ float spos[2][TMC];
    __shared__ float sneg[2][TMC];
    __shared__ float scolP[4][TNC];
    __shared__ float scolN[4][TNC];

    const int tid  = threadIdx.x;
    const int warp = tid >> 5;
    const int lane = tid & 31;
    const int g = lane >> 2;          // group id (row within 8)
    const int t = lane & 3;           // thread-in-group (16B row chunk)
    const int wm = warp >> 1;         // warp M index (0..3)
    const int wn = warp & 1;          // warp N index (0..1)

    // ---- decode triangular pair ----
    int bi = 0, rem = blockIdx.x;
    while (rem >= (NB - bi)) { rem -= (NB - bi); ++bi; }
    const int bj = bi + rem;
    const int i0 = bi * TMC;
    const int j0 = bj * TNC;
    const bool do_col = (bi != bj);

    const uint32_t dsm = s2u(dsm_raw);

    // column labels/weights
    if (tid < TNC) {
        int yy = y[j0 + tid];
        ysh[tid] = yy;
        wsh[tid] = g_invc[yy];
    }

    // ---- per-thread copy descriptors (4 x 16B per stage) ----
    const char* srcp[4];
    uint32_t    sdst[4];
#pragma unroll
    for (int j = 0; j < 4; ++j) {
        int u   = tid + 256 * j;      // 16B unit index 0..1023
        int row = u >> 2;             // 0..255
        int tt  = u & 3;
        int lr, grow; uint32_t base;
        if (row < TMC) { lr = row;        grow = i0 + lr; base = 0; }
        else           { lr = row - TMC;  grow = j0 + lr; base = A_ST_BYTES; }
        srcp[j] = (const char*)(g_qh + (size_t)grow * DIM) + tt * 16;
        sdst[j] = base + (uint32_t)lr * 64 + (uint32_t)((tt ^ ((lr >> 1) & 3)) * 16);
    }

    // ---- per-thread fragment read offsets (64B rows) ----
    uint32_t Aoff[2][2], Boff[8];
#pragma unroll
    for (int mt = 0; mt < 2; ++mt) {
#pragma unroll
        for (int hh = 0; hh < 2; ++hh) {
            int r = wm * 32 + mt * 16 + hh * 8 + g;
            Aoff[mt][hh] = (uint32_t)r * 64 + (uint32_t)((t ^ ((r >> 1) & 3)) * 16);
        }
    }
#pragma unroll
    for (int nt = 0; nt < 8; ++nt) {
        int r = wn * 64 + nt * 8 + g;
        Boff[nt] = A_ST_BYTES + (uint32_t)r * 64 + (uint32_t)((t ^ ((r >> 1) & 3)) * 16);
    }

    float c[2][8][4];
#pragma unroll
    for (int mt = 0; mt < 2; ++mt)
#pragma unroll
        for (int nt = 0; nt < 8; ++nt)
#pragma unroll
            for (int e = 0; e < 4; ++e) c[mt][nt][e] = 0.0f;

    // ---- prologue: stages 0..2 ----
#pragma unroll
    for (int s = 0; s < 3; ++s) {
        uint32_t sb = dsm + s * STAGE_BYTES;
#pragma unroll
        for (int j = 0; j < 4; ++j) cpasync16(sb + sdst[j], srcp[j] + s * 64);
        cp_commit();
    }

    // ---- main loop (16 k-steps of 32 halves) ----
#pragma unroll 1
    for (int kc = 0; kc < NKS; ++kc) {
        if (kc < NKS - 3) asm volatile("cp.async.wait_group 2;" ::: "memory");
        else              asm volatile("cp.async.wait_group 0;" ::: "memory");
        __syncthreads();

        if (kc + 3 < NKS) {
            int s = kc + 3;
            uint32_t sb = dsm + (s & 3) * STAGE_BYTES;
#pragma unroll
            for (int j = 0; j < 4; ++j) cpasync16(sb + sdst[j], srcp[j] + s * 64);
            cp_commit();
        }

        uint32_t sb = dsm + (kc & 3) * STAGE_BYTES;
        uint32_t a[2][8];
#pragma unroll
        for (int mt = 0; mt < 2; ++mt) {
            lds128(&a[mt][0], sb + Aoff[mt][0]);   // row g:   halves 8t..8t+7
            lds128(&a[mt][4], sb + Aoff[mt][1]);   // row g+8
        }
#pragma unroll
        for (int nt = 0; nt < 8; ++nt) {
            uint32_t b[4];
            lds128(b, sb + Boff[nt]);
#pragma unroll
            for (int mt = 0; mt < 2; ++mt) {
                MMA_F16(c[mt][nt], a[mt][0], a[mt][4], a[mt][1], a[mt][5], b[0], b[1]);
                MMA_F16(c[mt][nt], a[mt][2], a[mt][6], a[mt][3], a[mt][7], b[2], b[3]);
            }
        }
    }

    // ---- fused two-sided epilogue ----
    int   yrow[4];
    float winv[4];
#pragma unroll
    for (int mt = 0; mt < 2; ++mt)
#pragma unroll
        for (int hh = 0; hh < 2; ++hh) {
            int yy = y[i0 + wm * 32 + mt * 16 + hh * 8 + g];
            yrow[mt * 2 + hh] = yy;
            winv[mt * 2 + hh] = g_invc[yy];
        }

    float pos[4], neg[4];
    float colp[16], coln[16];
#pragma unroll
    for (int e = 0; e < 4; ++e)  { pos[e] = 0.0f;  neg[e] = 0.0f; }
#pragma unroll
    for (int e = 0; e < 16; ++e) { colp[e] = 0.0f; coln[e] = 0.0f; }

#pragma unroll
    for (int mt = 0; mt < 2; ++mt) {
        const int gr0 = i0 + wm * 32 + mt * 16 + g;     // rows for c0/c1
        const int gr1 = gr0 + 8;                        // rows for c2/c3
#pragma unroll
        for (int nt = 0; nt < 8; ++nt) {
            const int cl = wn * 64 + nt * 8 + 2 * t;
#pragma unroll
            for (int e = 0; e < 4; ++e) {
                const int col  = cl + (e & 1);
                const int grow = (e < 2) ? gr0 : gr1;
                const int idx  = mt * 2 + (e >> 1);
                const int ci   = nt * 2 + (e & 1);
                float d = c[mt][nt][e];
                float ev = ex2f(d * C2);
                bool nz   = (d != 0.0f);
                bool same = (ysh[col] == yrow[idx]);
                bool slf  = (j0 + col == grow);
                if (nz & same & !slf) pos[idx] += ev;
                if (nz & !same)       neg[idx] += ev * wsh[col];
                // transposed contribution (rows of bj get sums over this CTA's rows)
                if (nz & same)        colp[ci] += ev;
                if (nz & !same)       coln[ci] += ev * winv[idx];
            }
        }
    }

    // row reduce over the 4 lanes of each group (t axis)
#pragma unroll
    for (int e = 0; e < 4; ++e) {
        pos[e] += __shfl_xor_sync(0xffffffffu, pos[e], 1);
        pos[e] += __shfl_xor_sync(0xffffffffu, pos[e], 2);
        neg[e] += __shfl_xor_sync(0xffffffffu, neg[e], 1);
        neg[e] += __shfl_xor_sync(0xffffffffu, neg[e], 2);
    }
    if (t == 0) {
#pragma unroll
        for (int mt = 0; mt < 2; ++mt)
#pragma unroll
            for (int hh = 0; hh < 2; ++hh) {
                int r = wm * 32 + mt * 16 + hh * 8 + g;
                spos[wn][r] = pos[mt * 2 + hh];
                sneg[wn][r] = neg[mt * 2 + hh];
            }
    }

    // col reduce over the 8 groups (g axis)
#pragma unroll
    for (int e = 0; e < 16; ++e) {
        colp[e] += __shfl_xor_sync(0xffffffffu, colp[e], 4);
        colp[e] += __shfl_xor_sync(0xffffffffu, colp[e], 8);
        colp[e] += __shfl_xor_sync(0xffffffffu, colp[e], 16);
        coln[e] += __shfl_xor_sync(0xffffffffu, coln[e], 4);
        coln[e] += __shfl_xor_sync(0xffffffffu, coln[e], 8);
        coln[e] += __shfl_xor_sync(0xffffffffu, coln[e], 16);
    }
    if (g == 0) {  // lanes t=0..3 hold full g-sums
#pragma unroll
        for (int nt = 0; nt < 8; ++nt)
#pragma unroll
            for (int e01 = 0; e01 < 2; ++e01) {
                int col = wn * 64 + nt * 8 + 2 * t + e01;
                scolP[wm][col] = colp[nt * 2 + e01];
                scolN[wm][col] = coln[nt * 2 + e01];
            }
    }
    __syncthreads();
    if (tid < TMC) {
        float pp = spos[0][tid] + spos[1][tid];
        float nn = sneg[0][tid] + sneg[1][tid];
        g_posR[bj][i0 + tid] = pp;
        g_negR[bj][i0 + tid] = nn;
    }
    if (do_col && tid < TNC) {
        float pp = (scolP[0][tid] + scolP[1][tid]) + (scolP[2][tid] + scolP[3][tid]);
        float nn = (scolN[0][tid] + scolN[1][tid]) + (scolN[2][tid] + scolN[3][tid]);
        g_posC[bi][j0 + tid] = pp;
        g_negC[bi][j0 + tid] = nn;
    }
}

// ---------------- kernel 3: k-positive sims + per-row loss ----------------
__global__ void k_rowloss(const float* __restrict__ q,
                          const float* __restrict__ kv,
                          const int* __restrict__ y) {
    const int warp = threadIdx.x >> 5;
    const int lane = threadIdx.x & 31;
    const int i = blockIdx.x * 8 + warp;

    const float4* qi = (const float4*)(q + (size_t)i * DIM);
    float4 qreg[4];
#pragma unroll
    for (int e = 0; e < 4; ++e) qreg[e] = qi[lane + 32 * e];

    float esum = 0.0f;
#pragma unroll 1
    for (int kk = 0; kk < KPOS; kk += 2) {   // dual-kk for 2x MLP
        const float4* kp0 = (const float4*)(kv + ((size_t)i * KPOS + kk) * DIM);
        const float4* kp1 = (const float4*)(kv + ((size_t)i * KPOS + kk + 1) * DIM);
        float acc0 = 0.0f, acc1 = 0.0f;
#pragma unroll
        for (int e = 0; e < 4; ++e) {
            float4 b0 = kp0[lane + 32 * e];
            float4 b1 = kp1[lane + 32 * e];
            float4 a = qreg[e];
            acc0 = fmaf(a.x, b0.x, acc0); acc1 = fmaf(a.x, b1.x, acc1);
            acc0 = fmaf(a.y, b0.y, acc0); acc1 = fmaf(a.y, b1.y, acc1);
            acc0 = fmaf(a.z, b0.z, acc0); acc1 = fmaf(a.z, b1.z, acc1);
            acc0 = fmaf(a.w, b0.w, acc0); acc1 = fmaf(a.w, b1.w, acc1);
        }
#pragma unroll
        for (int off = 16; off > 0; off >>= 1) {
            acc0 += __shfl_down_sync(0xffffffffu, acc0, off);
            acc1 += __shfl_down_sync(0xffffffffu, acc1, off);
        }
        if (lane == 0) esum += ex2f(acc0 * C2) + ex2f(acc1 * C2);
    }

    // parallel slot gather: 64 slots per row, 2 per lane (fixed order -> deterministic)
    const int b = i >> 7;                 // 128-block of this row
    const int nR = NB - b;                // row-sum slot count
    float pt = 0.0f, nt = 0.0f;
#pragma unroll
    for (int hh = 0; hh < 2; ++hh) {
        int s = lane + 32 * hh;
        if (s < nR) { pt += g_posR[b + s][i];      nt += g_negR[b + s][i]; }
        else        { pt += g_posC[s - nR][i];     nt += g_negC[s - nR][i]; }
    }
#pragma unroll
    for (int off = 16; off > 0; off >>= 1) {
        pt += __shfl_down_sync(0xffffffffu, pt, off);
        nt += __shfl_down_sync(0xffffffffu, nt, off);
    }
    if (lane == 0) {
        pt += esum;
        float num = logf(pt);
        float den = logf(nt);
        float cnt = (float)(g_cnt[y[i]] - 1 + KPOS);
        g_loss[i] = -(num - den) / cnt;
    }
}

// ---------------- kernel 4: deterministic mean ----------------
__global__ void k_reduce(float* __restrict__ out) {
    __shared__ float sm[1024];
    const float4* l4 = (const float4*)g_loss;
    float4 v0 = l4[threadIdx.x];
    float4 v1 = l4[threadIdx.x + 1024];
    float s = ((v0.x + v0.y) + (v0.z + v0.w)) + ((v1.x + v1.y) + (v1.z + v1.w));
    sm[threadIdx.x] = s;
    __syncthreads();
    for (int st = 512; st > 0; st >>= 1) {
        if (threadIdx.x < st) sm[threadIdx.x] += sm[threadIdx.x + st];
        __syncthreads();
    }
    if (threadIdx.x == 0) out[0] = sm[0] * (1.0f / (float)N_ROWS);
}

// ---------------- launch ----------------
extern "C" void kernel_launch(void* const* d_in, const int* in_sizes, int n_in,
                              void* d_out, int out_size) {
    const float* q  = nullptr;
    const float* kv = nullptr;
    const int*   y  = nullptr;
    for (int i = 0; i < n_in; ++i) {
        long long sz = in_sizes[i];
        if (sz == (long long)N_ROWS * DIM)             q  = (const float*)d_in[i];
        else if (sz == (long long)N_ROWS * KPOS * DIM) kv = (const float*)d_in[i];
        else if (sz == (long long)N_ROWS)              y  = (const int*)d_in[i];
    }
    float* out = (float*)d_out;

    cudaFuncSetAttribute(k_gram, cudaFuncAttributeMaxDynamicSharedMemorySize, DSM_BYTES);

    k_bincount<<<1, 1024>>>(y);
    k_prep<<<(N_ROWS * DIM / 8) / 256, 256>>>(q);
    k_gram<<<NPAIRS, 256, DSM_BYTES>>>(y);
    k_rowloss<<<N_ROWS / 8, 256>>>(q, kv, y);
    k_reduce<<<1, 1024>>>(out);
}

// round 12
// speedup vs baseline: 18.9567x; 1.0390x over previous
#include <cuda_runtime.h>
#include <cuda_fp16.h>
#include <math.h>
#include <stdint.h>

// ---------------- problem shapes ----------------
#define N_ROWS 8192
#define DIM    512
#define KPOS   8
#define NCLS   1000
#define C2     20.60992915555662f   // log2(e)/0.07

// ---------------- GEMM tiling ----------------
#define TMC 128                    // CTA M tile
#define TNC 128                    // CTA N tile
#define KCH 32                     // K halves per stage (two m16n8k16 sub-steps)
#define NKS (DIM / KCH)            // 16 k-steps -> 8 pairs
#define NB  (N_ROWS / 128)         // 64 blocks of 128 (triangular pairing)
#define NPAIRS (NB * (NB + 1) / 2) // 2080 CTAs
#define A_ST_BYTES (TMC * KCH * 2) // 8192
#define B_ST_BYTES (TNC * KCH * 2) // 8192
#define STAGE_BYTES (A_ST_BYTES + B_ST_BYTES)  // 16384
#define NSTAGES 6
#define DSM_BYTES (NSTAGES * STAGE_BYTES)      // 98304

// ---------------- scratch ----------------
__device__ __align__(16) __half g_qh[N_ROWS * DIM];  // fp16 Q, row-major
__device__ float g_posR[NB][N_ROWS];       // tile (bi,bj) row sums -> slot bj
__device__ float g_negR[NB][N_ROWS];
__device__ float g_posC[NB][N_ROWS];       // tile (bi,bj) col sums -> slot bi (bi!=bj)
__device__ float g_negC[NB][N_ROWS];
__device__ int   g_cnt[NCLS];
__device__ float g_invc[NCLS];
__device__ float g_loss[N_ROWS];

// ---------------- helpers ----------------
__device__ __forceinline__ uint32_t s2u(const void* p) {
    uint32_t a;
    asm("{ .reg .u64 t; cvta.to.shared.u64 t, %1; cvt.u32.u64 %0, t; }" : "=r"(a) : "l"(p));
    return a;
}
__device__ __forceinline__ void lds128(uint32_t* r, uint32_t a) {
    asm volatile("ld.shared.v4.b32 {%0,%1,%2,%3}, [%4];"
                 : "=r"(r[0]), "=r"(r[1]), "=r"(r[2]), "=r"(r[3]) : "r"(a));
}
__device__ __forceinline__ void cpasync16(uint32_t dst, const void* src) {
    asm volatile("cp.async.cg.shared.global [%0], [%1], 16;" :: "r"(dst), "l"(src) : "memory");
}
__device__ __forceinline__ void cp_commit() {
    asm volatile("cp.async.commit_group;" ::: "memory");
}
__device__ __forceinline__ float ex2f(float x) {
    float r;
    asm("ex2.approx.ftz.f32 %0, %1;" : "=f"(r) : "f"(x));
    return r;
}
// fp16 mma, fp32 accum. k-slot permutation: sub-mma uses contiguous 16B row chunks.
#define MMA_F16(c, a0, a1, a2, a3, b0, b1)                                    \
    asm volatile(                                                             \
        "mma.sync.aligned.m16n8k16.row.col.f32.f16.f16.f32 "                  \
        "{%0,%1,%2,%3},{%4,%5,%6,%7},{%8,%9},{%0,%1,%2,%3};"                  \
        : "+f"(c[0]), "+f"(c[1]), "+f"(c[2]), "+f"(c[3])                      \
        : "r"(a0), "r"(a1), "r"(a2), "r"(a3), "r"(b0), "r"(b1))

// ---------------- kernel 0: bincount + reciprocals ----------------
__global__ void k_bincount(const int* __restrict__ y) {
    __shared__ int sc[NCLS];
    for (int c = threadIdx.x; c < NCLS; c += blockDim.x) sc[c] = 0;
    __syncthreads();
    for (int i = threadIdx.x; i < N_ROWS; i += blockDim.x)
        atomicAdd(&sc[y[i]], 1);
    __syncthreads();
    for (int c = threadIdx.x; c < NCLS; c += blockDim.x) {
        int v = sc[c];
        g_cnt[c]  = v;
        g_invc[c] = v > 0 ? 1.0f / (float)v : 0.0f;
    }
}

// ---------------- kernel 1: fp16-convert Q (row-major) ----------------
__global__ void k_prep(const float* __restrict__ q) {
    int gid = blockIdx.x * blockDim.x + threadIdx.x;  // 8 floats each
    const float4* q4 = (const float4*)q;
    float4 v0 = q4[gid * 2 + 0];
    float4 v1 = q4[gid * 2 + 1];
    __half2 h0 = __float22half2_rn(make_float2(v0.x, v0.y));
    __half2 h1 = __float22half2_rn(make_float2(v0.z, v0.w));
    __half2 h2 = __float22half2_rn(make_float2(v1.x, v1.y));
    __half2 h3 = __float22half2_rn(make_float2(v1.z, v1.w));
    uint4 o;
    o.x = *(uint32_t*)&h0; o.y = *(uint32_t*)&h1;
    o.z = *(uint32_t*)&h2; o.w = *(uint32_t*)&h3;
    ((uint4*)g_qh)[gid] = o;
}

// ---------------- kernel 2: triangular fp16 mma Gram + two-sided epilogue ----------------
// Pair (bi, bj), bi<=bj over 64 blocks of 128. CTA tile: rows [bi*128, +128),
// cols [bj*128, +128). Row sums -> slot bj; col sums -> slot bi (bi!=bj).
// 8 warps = 4(M) x 2(N), warp tile 32x64. 2 CTAs/SM. 6-stage pipe, barrier per step-pair.
__global__ __launch_bounds__(256, 2)
void k_gram(const int* __restrict__ y) {
    extern __shared__ __align__(16) char dsm_raw[];
    __shared__ int   ysh[TNC];
    __shared__ float wsh[TNC];
    __shared__ float spos[2][TMC];
    __shared__ float sneg[2][TMC];
    __shared__ float scolP[4][TNC];
    __shared__ float scolN[4][TNC];

    const int tid  = threadIdx.x;
    const int warp = tid >> 5;
    const int lane = tid & 31;
    const int g = lane >> 2;          // group id (row within 8)
    const int t = lane & 3;           // thread-in-group (16B row chunk)
    const int wm = warp >> 1;         // warp M index (0..3)
    const int wn = warp & 1;          // warp N index (0..1)

    // ---- decode triangular pair ----
    int bi = 0, rem = blockIdx.x;
    while (rem >= (NB - bi)) { rem -= (NB - bi); ++bi; }
    const int bj = bi + rem;
    const int i0 = bi * TMC;
    const int j0 = bj * TNC;
    const bool do_col = (bi != bj);

    const uint32_t dsm = s2u(dsm_raw);

    // column labels/weights
    if (tid < TNC) {
        int yy = y[j0 + tid];
        ysh[tid] = yy;
        wsh[tid] = g_invc[yy];
    }

    // ---- per-thread copy descriptors (4 x 16B per stage) ----
    const char* srcp[4];
    uint32_t    sdst[4];
#pragma unroll
    for (int j = 0; j < 4; ++j) {
        int u   = tid + 256 * j;      // 16B unit index 0..1023
        int row = u >> 2;             // 0..255
        int tt  = u & 3;
        int lr, grow; uint32_t base;
        if (row < TMC) { lr = row;        grow = i0 + lr; base = 0; }
        else           { lr = row - TMC;  grow = j0 + lr; base = A_ST_BYTES; }
        srcp[j] = (const char*)(g_qh + (size_t)grow * DIM) + tt * 16;
        sdst[j] = base + (uint32_t)lr * 64 + (uint32_t)((tt ^ ((lr >> 1) & 3)) * 16);
    }

    // ---- per-thread fragment read offsets (64B rows) ----
    uint32_t Aoff[2][2], Boff[8];
#pragma unroll
    for (int mt = 0; mt < 2; ++mt) {
#pragma unroll
        for (int hh = 0; hh < 2; ++hh) {
            int r = wm * 32 + mt * 16 + hh * 8 + g;
            Aoff[mt][hh] = (uint32_t)r * 64 + (uint32_t)((t ^ ((r >> 1) & 3)) * 16);
        }
    }
#pragma unroll
    for (int nt = 0; nt < 8; ++nt) {
        int r = wn * 64 + nt * 8 + g;
        Boff[nt] = A_ST_BYTES + (uint32_t)r * 64 + (uint32_t)((t ^ ((r >> 1) & 3)) * 16);
    }

    float c[2][8][4];
#pragma unroll
    for (int mt = 0; mt < 2; ++mt)
#pragma unroll
        for (int nt = 0; nt < 8; ++nt)
#pragma unroll
            for (int e = 0; e < 4; ++e) c[mt][nt][e] = 0.0f;

    // ---- prologue: pairs 0,1 (stages 0..3) ----
#pragma unroll
    for (int pp = 0; pp < 2; ++pp) {
#pragma unroll
        for (int h = 0; h < 2; ++h) {
            int s = 2 * pp + h;
            uint32_t sb = dsm + s * STAGE_BYTES;
#pragma unroll
            for (int j = 0; j < 4; ++j) cpasync16(sb + sdst[j], srcp[j] + s * 64);
        }
        cp_commit();
    }

    // ---- main loop: 8 step-pairs, one barrier each ----
    int b0 = 0;   // buffer index of first stage of this pair
#pragma unroll 1
    for (int p = 0; p < NKS / 2; ++p) {
        if (p < NKS / 2 - 1) asm volatile("cp.async.wait_group 1;" ::: "memory");
        else                 asm volatile("cp.async.wait_group 0;" ::: "memory");
        __syncthreads();

        if (p + 2 < NKS / 2) {
            int pb = b0 + 4; if (pb >= NSTAGES) pb -= NSTAGES;
            int s0 = 2 * (p + 2);
#pragma unroll
            for (int h = 0; h < 2; ++h) {
                uint32_t sb = dsm + (pb + h) * STAGE_BYTES;
#pragma unroll
                for (int j = 0; j < 4; ++j) cpasync16(sb + sdst[j], srcp[j] + (s0 + h) * 64);
            }
            cp_commit();
        }

#pragma unroll
        for (int h = 0; h < 2; ++h) {
            uint32_t sb = dsm + (b0 + h) * STAGE_BYTES;
            uint32_t a[2][8];
#pragma unroll
            for (int mt = 0; mt < 2; ++mt) {
                lds128(&a[mt][0], sb + Aoff[mt][0]);   // row g:   halves 8t..8t+7
                lds128(&a[mt][4], sb + Aoff[mt][1]);   // row g+8
            }
            uint32_t bb[2][4];
            lds128(bb[0], sb + Boff[0]);
#pragma unroll
            for (int nt = 0; nt < 8; ++nt) {
                if (nt < 7) lds128(bb[(nt + 1) & 1], sb + Boff[nt + 1]);
                uint32_t* bv = bb[nt & 1];
#pragma unroll
                for (int mt = 0; mt < 2; ++mt) {
                    MMA_F16(c[mt][nt], a[mt][0], a[mt][4], a[mt][1], a[mt][5], bv[0], bv[1]);
                    MMA_F16(c[mt][nt], a[mt][2], a[mt][6], a[mt][3], a[mt][7], bv[2], bv[3]);
                }
            }
        }
        b0 += 2; if (b0 >= NSTAGES) b0 = 0;
    }

    // ---- fused two-sided epilogue ----
    int   yrow[4];
    float winv[4];
#pragma unroll
    for (int mt = 0; mt < 2; ++mt)
#pragma unroll
        for (int hh = 0; hh < 2; ++hh) {
            int yy = y[i0 + wm * 32 + mt * 16 + hh * 8 + g];
            yrow[mt * 2 + hh] = yy;
            winv[mt * 2 + hh] = g_invc[yy];
        }

    float pos[4], neg[4];
    float colp[16], coln[16];
#pragma unroll
    for (int e = 0; e < 4; ++e)  { pos[e] = 0.0f;  neg[e] = 0.0f; }
#pragma unroll
    for (int e = 0; e < 16; ++e) { colp[e] = 0.0f; coln[e] = 0.0f; }

#pragma unroll
    for (int mt = 0; mt < 2; ++mt) {
        const int gr0 = i0 + wm * 32 + mt * 16 + g;     // rows for c0/c1
        const int gr1 = gr0 + 8;                        // rows for c2/c3
#pragma unroll
        for (int nt = 0; nt < 8; ++nt) {
            const int cl = wn * 64 + nt * 8 + 2 * t;
#pragma unroll
            for (int e = 0; e < 4; ++e) {
                const int col  = cl + (e & 1);
                const int grow = (e < 2) ? gr0 : gr1;
                const int idx  = mt * 2 + (e >> 1);
                const int ci   = nt * 2 + (e & 1);
                float d = c[mt][nt][e];
                float ev = ex2f(d * C2);
                bool nz   = (d != 0.0f);
                bool same = (ysh[col] == yrow[idx]);
                bool slf  = (j0 + col == grow);
                if (nz & same & !slf) pos[idx] += ev;
                if (nz & !same)       neg[idx] += ev * wsh[col];
                // transposed contribution (rows of bj get sums over this CTA's rows)
                if (nz & same)        colp[ci] += ev;
                if (nz & !same)       coln[ci] += ev * winv[idx];
            }
        }
    }

    // row reduce over the 4 lanes of each group (t axis)
#pragma unroll
    for (int e = 0; e < 4; ++e) {
        pos[e] += __shfl_xor_sync(0xffffffffu, pos[e], 1);
        pos[e] += __shfl_xor_sync(0xffffffffu, pos[e], 2);
        neg[e] += __shfl_xor_sync(0xffffffffu, neg[e], 1);
        neg[e] += __shfl_xor_sync(0xffffffffu, neg[e], 2);
    }
    if (t == 0) {
#pragma unroll
        for (int mt = 0; mt < 2; ++mt)
#pragma unroll
            for (int hh = 0; hh < 2; ++hh) {
                int r = wm * 32 + mt * 16 + hh * 8 + g;
                spos[wn][r] = pos[mt * 2 + hh];
                sneg[wn][r] = neg[mt * 2 + hh];
            }
    }

    // col reduce over the 8 groups (g axis)
#pragma unroll
    for (int e = 0; e < 16; ++e) {
        colp[e] += __shfl_xor_sync(0xffffffffu, colp[e], 4);
        colp[e] += __shfl_xor_sync(0xffffffffu, colp[e], 8);
        colp[e] += __shfl_xor_sync(0xffffffffu, colp[e], 16);
        coln[e] += __shfl_xor_sync(0xffffffffu, coln[e], 4);
        coln[e] += __shfl_xor_sync(0xffffffffu, coln[e], 8);
        coln[e] += __shfl_xor_sync(0xffffffffu, coln[e], 16);
    }
    if (g == 0) {  // lanes t=0..3 hold full g-sums
#pragma unroll
        for (int nt = 0; nt < 8; ++nt)
#pragma unroll
            for (int e01 = 0; e01 < 2; ++e01) {
                int col = wn * 64 + nt * 8 + 2 * t + e01;
                scolP[wm][col] = colp[nt * 2 + e01];
                scolN[wm][col] = coln[nt * 2 + e01];
            }
    }
    __syncthreads();
    if (tid < TMC) {
        float pp = spos[0][tid] + spos[1][tid];
        float nn = sneg[0][tid] + sneg[1][tid];
        g_posR[bj][i0 + tid] = pp;
        g_negR[bj][i0 + tid] = nn;
    }
    if (do_col && tid < TNC) {
        float pp = (scolP[0][tid] + scolP[1][tid]) + (scolP[2][tid] + scolP[3][tid]);
        float nn = (scolN[0][tid] + scolN[1][tid]) + (scolN[2][tid] + scolN[3][tid]);
        g_posC[bi][j0 + tid] = pp;
        g_negC[bi][j0 + tid] = nn;
    }
}

// ---------------- kernel 3: k-positive sims + per-row loss ----------------
__global__ void k_rowloss(const float* __restrict__ q,
                          const float* __restrict__ kv,
                          const int* __restrict__ y) {
    const int warp = threadIdx.x >> 5;
    const int lane = threadIdx.x & 31;
    const int i = blockIdx.x * 8 + warp;

    const float4* qi = (const float4*)(q + (size_t)i * DIM);
    float4 qreg[4];
#pragma unroll
    for (int e = 0; e < 4; ++e) qreg[e] = qi[lane + 32 * e];

    float esum = 0.0f;
#pragma unroll 1
    for (int r = 0; r < 2; ++r) {        // 2 rounds of 4 kk -> 16 outstanding float4 loads
        float4 bld[4][4];
#pragma unroll
        for (int k4 = 0; k4 < 4; ++k4) {
            const float4* kp = (const float4*)(kv + ((size_t)i * KPOS + r * 4 + k4) * DIM);
#pragma unroll
            for (int e = 0; e < 4; ++e) bld[k4][e] = kp[lane + 32 * e];
        }
        float acc[4] = {0.0f, 0.0f, 0.0f, 0.0f};
#pragma unroll
        for (int k4 = 0; k4 < 4; ++k4)
#pragma unroll
            for (int e = 0; e < 4; ++e) {
                acc[k4] = fmaf(qreg[e].x, bld[k4][e].x, acc[k4]);
                acc[k4] = fmaf(qreg[e].y, bld[k4][e].y, acc[k4]);
                acc[k4] = fmaf(qreg[e].z, bld[k4][e].z, acc[k4]);
                acc[k4] = fmaf(qreg[e].w, bld[k4][e].w, acc[k4]);
            }
#pragma unroll
        for (int k4 = 0; k4 < 4; ++k4) {
#pragma unroll
            for (int off = 16; off > 0; off >>= 1)
                acc[k4] += __shfl_down_sync(0xffffffffu, acc[k4], off);
            if (lane == 0) esum += ex2f(acc[k4] * C2);
        }
    }

    // parallel slot gather: 64 slots per row, 2 per lane (fixed order -> deterministic)
    const int b = i >> 7;                 // 128-block of this row
    const int nR = NB - b;                // row-sum slot count
    float pt = 0.0f, nt = 0.0f;
#pragma unroll
    for (int hh = 0; hh < 2; ++hh) {
        int s = lane + 32 * hh;
        if (s < nR) { pt += g_posR[b + s][i];      nt += g_negR[b + s][i]; }
        else        { pt += g_posC[s - nR][i];     nt += g_negC[s - nR][i]; }
    }
#pragma unroll
    for (int off = 16; off > 0; off >>= 1) {
        pt += __shfl_down_sync(0xffffffffu, pt, off);
        nt += __shfl_down_sync(0xffffffffu, nt, off);
    }
    if (lane == 0) {
        pt += esum;
        float num = logf(pt);
        float den = logf(nt);
        float cnt = (float)(g_cnt[y[i]] - 1 + KPOS);
        g_loss[i] = -(num - den) / cnt;
    }
}

// ---------------- kernel 4: deterministic mean ----------------
__global__ void k_reduce(float* __restrict__ out) {
    __shared__ float sm[1024];
    const float4* l4 = (const float4*)g_loss;
    float4 v0 = l4[threadIdx.x];
    float4 v1 = l4[threadIdx.x + 1024];
    float s = ((v0.x + v0.y) + (v0.z + v0.w)) + ((v1.x + v1.y) + (v1.z + v1.w));
    sm[threadIdx.x] = s;
    __syncthreads();
    for (int st = 512; st > 0; st >>= 1) {
        if (threadIdx.x < st) sm[threadIdx.x] += sm[threadIdx.x + st];
        __syncthreads();
    }
    if (threadIdx.x == 0) out[0] = sm[0] * (1.0f / (float)N_ROWS);
}

// ---------------- launch ----------------
extern "C" void kernel_launch(void* const* d_in, const int* in_sizes, int n_in,
                              void* d_out, int out_size) {
    const float* q  = nullptr;
    const float* kv = nullptr;
    const int*   y  = nullptr;
    for (int i = 0; i < n_in; ++i) {
        long long sz = in_sizes[i];
        if (sz == (long long)N_ROWS * DIM)             q  = (const float*)d_in[i];
        else if (sz == (long long)N_ROWS * KPOS * DIM) kv = (const float*)d_in[i];
        else if (sz == (long long)N_ROWS)              y  = (const int*)d_in[i];
    }
    float* out = (float*)d_out;

    cudaFuncSetAttribute(k_gram, cudaFuncAttributeMaxDynamicSharedMemorySize, DSM_BYTES);

    k_bincount<<<1, 1024>>>(y);
    k_prep<<<(N_ROWS * DIM / 8) / 256, 256>>>(q);
    k_gram<<<NPAIRS, 256, DSM_BYTES>>>(y);
    k_rowloss<<<N_ROWS / 8, 256>>>(q, kv, y);
    k_reduce<<<1, 1024>>>(out);
}

// round 16
// speedup vs baseline: 20.0762x; 1.0591x over previous
#include <cuda_runtime.h>
#include <cuda_fp16.h>
#include <math.h>
#include <stdint.h>

// ---------------- problem shapes ----------------
#define N_ROWS 8192
#define DIM    512
#define KPOS   8
#define NCLS   1000
#define C2     20.60992915555662f   // log2(e)/0.07

// ---------------- GEMM tiling ----------------
#define TMC 128                    // CTA M tile
#define TNC 128                    // CTA N tile
#define KCH 32                     // K halves per stage (two m16n8k16 sub-steps)
#define NKS (DIM / KCH)            // 16 k-steps -> 8 pairs
#define NB  (N_ROWS / 128)         // 64 blocks of 128 (triangular pairing)
#define NPAIRS (NB * (NB + 1) / 2) // 2080 CTAs
#define A_ST_BYTES (TMC * KCH * 2) // 8192
#define B_ST_BYTES (TNC * KCH * 2) // 8192
#define STAGE_BYTES (A_ST_BYTES + B_ST_BYTES)  // 16384
#define NSTAGES 6
#define DSM_BYTES (NSTAGES * STAGE_BYTES)      // 98304

// ---------------- scratch ----------------
__device__ __align__(16) __half g_qh[N_ROWS * DIM];  // fp16 Q, row-major
__device__ float g_posR[NB][N_ROWS];       // tile (bi,bj) row sums -> slot bj
__device__ float g_negR[NB][N_ROWS];
__device__ float g_posC[NB][N_ROWS];       // tile (bi,bj) col sums -> slot bi (bi!=bj)
__device__ float g_negC[NB][N_ROWS];
__device__ int   g_cnt[NCLS];
__device__ float g_invc[NCLS];
__device__ float g_loss[N_ROWS];

// ---------------- helpers ----------------
__device__ __forceinline__ uint32_t s2u(const void* p) {
    uint32_t a;
    asm("{ .reg .u64 t; cvta.to.shared.u64 t, %1; cvt.u32.u64 %0, t; }" : "=r"(a) : "l"(p));
    return a;
}
__device__ __forceinline__ void lds128(uint32_t* r, uint32_t a) {
    asm volatile("ld.shared.v4.b32 {%0,%1,%2,%3}, [%4];"
                 : "=r"(r[0]), "=r"(r[1]), "=r"(r[2]), "=r"(r[3]) : "r"(a));
}
__device__ __forceinline__ void cpasync16(uint32_t dst, const void* src) {
    asm volatile("cp.async.cg.shared.global [%0], [%1], 16;" :: "r"(dst), "l"(src) : "memory");
}
__device__ __forceinline__ void cp_commit() {
    asm volatile("cp.async.commit_group;" ::: "memory");
}
__device__ __forceinline__ float ex2f(float x) {
    float r;
    asm("ex2.approx.ftz.f32 %0, %1;" : "=f"(r) : "f"(x));
    return r;
}
// fp16 mma, fp32 accum. k-slot permutation: sub-mma uses contiguous 16B row chunks.
#define MMA_F16(c, a0, a1, a2, a3, b0, b1)                                    \
    asm volatile(                                                             \
        "mma.sync.aligned.m16n8k16.row.col.f32.f16.f16.f32 "                  \
        "{%0,%1,%2,%3},{%4,%5,%6,%7},{%8,%9},{%0,%1,%2,%3};"                  \
        : "+f"(c[0]), "+f"(c[1]), "+f"(c[2]), "+f"(c[3])                      \
        : "r"(a0), "r"(a1), "r"(a2), "r"(a3), "r"(b0), "r"(b1))

// ---------------- kernel 1: fp16-convert Q + fused bincount (block 0) ----------------
__global__ void k_prep(const float* __restrict__ q, const int* __restrict__ y) {
    if (blockIdx.x == 0) {
        __shared__ int sc[NCLS];
        for (int c = threadIdx.x; c < NCLS; c += blockDim.x) sc[c] = 0;
        __syncthreads();
        for (int i = threadIdx.x; i < N_ROWS; i += blockDim.x)
            atomicAdd(&sc[y[i]], 1);
        __syncthreads();
        for (int c = threadIdx.x; c < NCLS; c += blockDim.x) {
            int v = sc[c];
            g_cnt[c]  = v;
            g_invc[c] = v > 0 ? 1.0f / (float)v : 0.0f;
        }
    }
    int gid = blockIdx.x * blockDim.x + threadIdx.x;  // 8 floats each
    const float4* q4 = (const float4*)q;
    float4 v0 = q4[gid * 2 + 0];
    float4 v1 = q4[gid * 2 + 1];
    __half2 h0 = __float22half2_rn(make_float2(v0.x, v0.y));
    __half2 h1 = __float22half2_rn(make_float2(v0.z, v0.w));
    __half2 h2 = __float22half2_rn(make_float2(v1.x, v1.y));
    __half2 h3 = __float22half2_rn(make_float2(v1.z, v1.w));
    uint4 o;
    o.x = *(uint32_t*)&h0; o.y = *(uint32_t*)&h1;
    o.z = *(uint32_t*)&h2; o.w = *(uint32_t*)&h3;
    ((uint4*)g_qh)[gid] = o;
}

// ---------------- kernel 2: triangular fp16 mma Gram + two-sided epilogue ----------------
// Pair (bi, bj), bi<=bj over 64 blocks of 128. CTA tile: rows [bi*128, +128),
// cols [bj*128, +128). Row sums -> slot bj; col sums -> slot bi (bi!=bj).
// 8 warps = 4(M) x 2(N), warp tile 32x64. 2 CTAs/SM. 6-stage pipe, barrier per step-pair.
__global__ __launch_bounds__(256, 2)
void k_gram(const int* __restrict__ y) {
    extern __shared__ __align__(16) char dsm_raw[];
    __shared__ int   ysh[TNC];
    __shared__ float wsh[TNC];
    __shared__ float spos[2][TMC];
    __shared__ float sneg[2][TMC];
    __shared__ float scolP[4][TNC];
    __shared__ float scolN[4][TNC];

    const int tid  = threadIdx.x;
    const int warp = tid >> 5;
    const int lane = tid & 31;
    const int g = lane >> 2;          // group id (row within 8)
    const int t = lane & 3;           // thread-in-group (16B row chunk)
    const int wm = warp >> 1;         // warp M index (0..3)
    const int wn = warp & 1;          // warp N index (0..1)

    // ---- decode triangular pair ----
    int bi = 0, rem = blockIdx.x;
    while (rem >= (NB - bi)) { rem -= (NB - bi); ++bi; }
    const int bj = bi + rem;
    const int i0 = bi * TMC;
    const int j0 = bj * TNC;
    const bool do_col = (bi != bj);

    const uint32_t dsm = s2u(dsm_raw);

    // column labels/weights
    if (tid < TNC) {
        int yy = y[j0 + tid];
        ysh[tid] = yy;
        wsh[tid] = g_invc[yy];
    }

    // ---- per-thread copy descriptors (4 x 16B per stage) ----
    const char* srcp[4];
    uint32_t    sdst[4];
#pragma unroll
    for (int j = 0; j < 4; ++j) {
        int u   = tid + 256 * j;      // 16B unit index 0..1023
        int row = u >> 2;             // 0..255
        int tt  = u & 3;
        int lr, grow; uint32_t base;
        if (row < TMC) { lr = row;        grow = i0 + lr; base = 0; }
        else           { lr = row - TMC;  grow = j0 + lr; base = A_ST_BYTES; }
        srcp[j] = (const char*)(g_qh + (size_t)grow * DIM) + tt * 16;
        sdst[j] = base + (uint32_t)lr * 64 + (uint32_t)((tt ^ ((lr >> 1) & 3)) * 16);
    }

    // ---- per-thread fragment read offsets (64B rows) ----
    uint32_t Aoff[2][2], Boff[8];
#pragma unroll
    for (int mt = 0; mt < 2; ++mt) {
#pragma unroll
        for (int hh = 0; hh < 2; ++hh) {
            int r = wm * 32 + mt * 16 + hh * 8 + g;
            Aoff[mt][hh] = (uint32_t)r * 64 + (uint32_t)((t ^ ((r >> 1) & 3)) * 16);
        }
    }
#pragma unroll
    for (int nt = 0; nt < 8; ++nt) {
        int r = wn * 64 + nt * 8 + g;
        Boff[nt] = A_ST_BYTES + (uint32_t)r * 64 + (uint32_t)((t ^ ((r >> 1) & 3)) * 16);
    }

    float c[2][8][4];
#pragma unroll
    for (int mt = 0; mt < 2; ++mt)
#pragma unroll
        for (int nt = 0; nt < 8; ++nt)
#pragma unroll
            for (int e = 0; e < 4; ++e) c[mt][nt][e] = 0.0f;

    // ---- prologue: pairs 0,1 (stages 0..3) ----
#pragma unroll
    for (int pp = 0; pp < 2; ++pp) {
#pragma unroll
        for (int h = 0; h < 2; ++h) {
            int s = 2 * pp + h;
            uint32_t sb = dsm + s * STAGE_BYTES;
#pragma unroll
            for (int j = 0; j < 4; ++j) cpasync16(sb + sdst[j], srcp[j] + s * 64);
        }
        cp_commit();
    }

    // ---- main loop: 8 step-pairs, one barrier each ----
    int b0 = 0;   // buffer index of first stage of this pair
#pragma unroll 1
    for (int p = 0; p < NKS / 2; ++p) {
        if (p < NKS / 2 - 1) asm volatile("cp.async.wait_group 1;" ::: "memory");
        else                 asm volatile("cp.async.wait_group 0;" ::: "memory");
        __syncthreads();

        if (p + 2 < NKS / 2) {
            int pb = b0 + 4; if (pb >= NSTAGES) pb -= NSTAGES;
            int s0 = 2 * (p + 2);
#pragma unroll
            for (int h = 0; h < 2; ++h) {
                uint32_t sb = dsm + (pb + h) * STAGE_BYTES;
#pragma unroll
                for (int j = 0; j < 4; ++j) cpasync16(sb + sdst[j], srcp[j] + (s0 + h) * 64);
            }
            cp_commit();
        }

#pragma unroll
        for (int h = 0; h < 2; ++h) {
            uint32_t sb = dsm + (b0 + h) * STAGE_BYTES;
            uint32_t a[2][8];
#pragma unroll
            for (int mt = 0; mt < 2; ++mt) {
                lds128(&a[mt][0], sb + Aoff[mt][0]);   // row g:   halves 8t..8t+7
                lds128(&a[mt][4], sb + Aoff[mt][1]);   // row g+8
            }
            uint32_t bb[2][4];
            lds128(bb[0], sb + Boff[0]);
#pragma unroll
            for (int nt = 0; nt < 8; ++nt) {
                if (nt < 7) lds128(bb[(nt + 1) & 1], sb + Boff[nt + 1]);
                uint32_t* bv = bb[nt & 1];
#pragma unroll
                for (int mt = 0; mt < 2; ++mt) {
                    MMA_F16(c[mt][nt], a[mt][0], a[mt][4], a[mt][1], a[mt][5], bv[0], bv[1]);
                    MMA_F16(c[mt][nt], a[mt][2], a[mt][6], a[mt][3], a[mt][7], bv[2], bv[3]);
                }
            }
        }
        b0 += 2; if (b0 >= NSTAGES) b0 = 0;
    }

    // ---- fused two-sided epilogue ----
    int   yrow[4];
    float winv[4];
#pragma unroll
    for (int mt = 0; mt < 2; ++mt)
#pragma unroll
        for (int hh = 0; hh < 2; ++hh) {
            int yy = y[i0 + wm * 32 + mt * 16 + hh * 8 + g];
            yrow[mt * 2 + hh] = yy;
            winv[mt * 2 + hh] = g_invc[yy];
        }

    float pos[4], neg[4];
    float colp[16], coln[16];
#pragma unroll
    for (int e = 0; e < 4; ++e)  { pos[e] = 0.0f;  neg[e] = 0.0f; }
#pragma unroll
    for (int e = 0; e < 16; ++e) { colp[e] = 0.0f; coln[e] = 0.0f; }

#pragma unroll
    for (int mt = 0; mt < 2; ++mt) {
        const int gr0 = i0 + wm * 32 + mt * 16 + g;     // rows for c0/c1
        const int gr1 = gr0 + 8;                        // rows for c2/c3
#pragma unroll
        for (int nt = 0; nt < 8; ++nt) {
            const int cl = wn * 64 + nt * 8 + 2 * t;
#pragma unroll
            for (int e = 0; e < 4; ++e) {
                const int col  = cl + (e & 1);
                const int grow = (e < 2) ? gr0 : gr1;
                const int idx  = mt * 2 + (e >> 1);
                const int ci   = nt * 2 + (e & 1);
                float d = c[mt][nt][e];
                float ev = ex2f(d * C2);
                bool nz   = (d != 0.0f);
                bool same = (ysh[col] == yrow[idx]);
                bool slf  = (j0 + col == grow);
                if (nz & same & !slf) pos[idx] += ev;
                if (nz & !same)       neg[idx] += ev * wsh[col];
                // transposed contribution (rows of bj get sums over this CTA's rows)
                if (nz & same)        colp[ci] += ev;
                if (nz & !same)       coln[ci] += ev * winv[idx];
            }
        }
    }

    // row reduce over the 4 lanes of each group (t axis)
#pragma unroll
    for (int e = 0; e < 4; ++e) {
        pos[e] += __shfl_xor_sync(0xffffffffu, pos[e], 1);
        pos[e] += __shfl_xor_sync(0xffffffffu, pos[e], 2);
        neg[e] += __shfl_xor_sync(0xffffffffu, neg[e], 1);
        neg[e] += __shfl_xor_sync(0xffffffffu, neg[e], 2);
    }
    if (t == 0) {
#pragma unroll
        for (int mt = 0; mt < 2; ++mt)
#pragma unroll
            for (int hh = 0; hh < 2; ++hh) {
                int r = wm * 32 + mt * 16 + hh * 8 + g;
                spos[wn][r] = pos[mt * 2 + hh];
                sneg[wn][r] = neg[mt * 2 + hh];
            }
    }

    // col reduce over the 8 groups (g axis)
#pragma unroll
    for (int e = 0; e < 16; ++e) {
        colp[e] += __shfl_xor_sync(0xffffffffu, colp[e], 4);
        colp[e] += __shfl_xor_sync(0xffffffffu, colp[e], 8);
        colp[e] += __shfl_xor_sync(0xffffffffu, colp[e], 16);
        coln[e] += __shfl_xor_sync(0xffffffffu, coln[e], 4);
        coln[e] += __shfl_xor_sync(0xffffffffu, coln[e], 8);
        coln[e] += __shfl_xor_sync(0xffffffffu, coln[e], 16);
    }
    if (g == 0) {  // lanes t=0..3 hold full g-sums
#pragma unroll
        for (int nt = 0; nt < 8; ++nt)
#pragma unroll
            for (int e01 = 0; e01 < 2; ++e01) {
                int col = wn * 64 + nt * 8 + 2 * t + e01;
                scolP[wm][col] = colp[nt * 2 + e01];
                scolN[wm][col] = coln[nt * 2 + e01];
            }
    }
    __syncthreads();
    if (tid < TMC) {
        float pp = spos[0][tid] + spos[1][tid];
        float nn = sneg[0][tid] + sneg[1][tid];
        g_posR[bj][i0 + tid] = pp;
        g_negR[bj][i0 + tid] = nn;
    }
    if (do_col && tid < TNC) {
        float pp = (scolP[0][tid] + scolP[1][tid]) + (scolP[2][tid] + scolP[3][tid]);
        float nn = (scolN[0][tid] + scolN[1][tid]) + (scolN[2][tid] + scolN[3][tid]);
        g_posC[bi][j0 + tid] = pp;
        g_negC[bi][j0 + tid] = nn;
    }
}

// ---------------- kernel 3: k-positive sims + per-row loss ----------------
// 2 warps per row: warp half h handles kk in [4h, 4h+4). Slot-gather loads issued
// up-front (independent L2 reads) so they complete under the kv dot products.
__global__ __launch_bounds__(256)
void k_rowloss(const float* __restrict__ q,
               const float* __restrict__ kv,
               const int* __restrict__ y) {
    __shared__ float sesum[8];
    const int warp = threadIdx.x >> 5;
    const int lane = threadIdx.x & 31;
    const int rloc = warp >> 1;          // 0..3
    const int half = warp & 1;
    const int i = blockIdx.x * 4 + rloc;

    // early-issue slot gather (half 0 warps): 64 slots, 2 per lane, fixed order
    const int b = i >> 7;
    const int nR = NB - b;
    float ptg[2] = {0.0f, 0.0f}, ntg[2] = {0.0f, 0.0f};
    if (half == 0) {
#pragma unroll
        for (int hh = 0; hh < 2; ++hh) {
            int s = lane + 32 * hh;
            if (s < nR) { ptg[hh] = g_posR[b + s][i];   ntg[hh] = g_negR[b + s][i]; }
            else        { ptg[hh] = g_posC[s - nR][i];  ntg[hh] = g_negC[s - nR][i]; }
        }
    }

    const float4* qi = (const float4*)(q + (size_t)i * DIM);
    float4 qreg[4];
#pragma unroll
    for (int e = 0; e < 4; ++e) qreg[e] = qi[lane + 32 * e];

    // one batch: 16 streaming float4 loads in flight per thread
    float4 bld[4][4];
#pragma unroll
    for (int k4 = 0; k4 < 4; ++k4) {
        const float4* kp = (const float4*)(kv + ((size_t)i * KPOS + half * 4 + k4) * DIM);
#pragma unroll
        for (int e = 0; e < 4; ++e) bld[k4][e] = __ldcs(kp + lane + 32 * e);
    }
    float acc[4] = {0.0f, 0.0f, 0.0f, 0.0f};
#pragma unroll
    for (int k4 = 0; k4 < 4; ++k4)
#pragma unroll
        for (int e = 0; e < 4; ++e) {
            acc[k4] = fmaf(qreg[e].x, bld[k4][e].x, acc[k4]);
            acc[k4] = fmaf(qreg[e].y, bld[k4][e].y, acc[k4]);
            acc[k4] = fmaf(qreg[e].z, bld[k4][e].z, acc[k4]);
            acc[k4] = fmaf(qreg[e].w, bld[k4][e].w, acc[k4]);
        }
    float esum = 0.0f;
#pragma unroll
    for (int k4 = 0; k4 < 4; ++k4) {
#pragma unroll
        for (int off = 16; off > 0; off >>= 1)
            acc[k4] += __shfl_down_sync(0xffffffffu, acc[k4], off);
        if (lane == 0) esum += ex2f(acc[k4] * C2);
    }
    if (lane == 0) sesum[warp] = esum;
    __syncthreads();

    if (half == 0) {
        float pt = ptg[0] + ptg[1];
        float nt = ntg[0] + ntg[1];
#pragma unroll
        for (int off = 16; off > 0; off >>= 1) {
            pt += __shfl_down_sync(0xffffffffu, pt, off);
            nt += __shfl_down_sync(0xffffffffu, nt, off);
        }
        if (lane == 0) {
            pt += sesum[2 * rloc] + sesum[2 * rloc + 1];
            float num = logf(pt);
            float den = logf(nt);
            float cnt = (float)(g_cnt[y[i]] - 1 + KPOS);
            g_loss[i] = -(num - den) / cnt;
        }
    }
}

// ---------------- kernel 4: deterministic mean ----------------
__global__ void k_reduce(float* __restrict__ out) {
    __shared__ float sm[1024];
    const float4* l4 = (const float4*)g_loss;
    float4 v0 = l4[threadIdx.x];
    float4 v1 = l4[threadIdx.x + 1024];
    float s = ((v0.x + v0.y) + (v0.z + v0.w)) + ((v1.x + v1.y) + (v1.z + v1.w));
    sm[threadIdx.x] = s;
    __syncthreads();
    for (int st = 512; st > 0; st >>= 1) {
        if (threadIdx.x < st) sm[threadIdx.x] += sm[threadIdx.x + st];
        __syncthreads();
    }
    if (threadIdx.x == 0) out[0] = sm[0] * (1.0f / (float)N_ROWS);
}

// ---------------- launch ----------------
extern "C" void kernel_launch(void* const* d_in, const int* in_sizes, int n_in,
                              void* d_out, int out_size) {
    const float* q  = nullptr;
    const float* kv = nullptr;
    const int*   y  = nullptr;
    for (int i = 0; i < n_in; ++i) {
        long long sz = in_sizes[i];
        if (sz == (long long)N_ROWS * DIM)             q  = (const float*)d_in[i];
        else if (sz == (long long)N_ROWS * KPOS * DIM) kv = (const float*)d_in[i];
        else if (sz == (long long)N_ROWS)              y  = (const int*)d_in[i];
    }
    float* out = (float*)d_out;

    cudaFuncSetAttribute(k_gram, cudaFuncAttributeMaxDynamicSharedMemorySize, DSM_BYTES);

    k_prep<<<(N_ROWS * DIM / 8) / 256, 256>>>(q, y);
    k_gram<<<NPAIRS, 256, DSM_BYTES>>>(y);
    k_rowloss<<<N_ROWS / 4, 256>>>(q, kv, y);
    k_reduce<<<1, 1024>>>(out);
}